// round 1
// baseline (speedup 1.0000x reference)
#include <cuda_runtime.h>
#include <math.h>

#define VV 3
#define CC 32
#define DD 48
#define HH 128
#define WW 160
#define HW (HH*WW)        /* 20480 */
#define DHW (DD*HW)       /* 983040 */

// ---------------------------------------------------------------------------
// Scratch (static device globals; allocation inside kernel_launch is banned)
// ---------------------------------------------------------------------------
__device__ float g_xform[2][12];                 // rot(9)+trans(3) per src view
__device__ float g_feat_t[(size_t)VV*HW*CC];     // channels-last features
__device__ float g_var[(size_t)DHW*CC];          // variance volume [D,H,W,32]
__device__ float g_h0[(size_t)DHW*8];            // conv0 out [D,H,W,8]
__device__ float g_h1[(size_t)DHW*8];            // conv1 out [D,H,W,8]
__device__ float g_cost[(size_t)DHW];            // conv2 out [D,H,W]

// ---------------------------------------------------------------------------
// Kernel 1: projective transforms  M_v = C_v * inv(C_0)  (1 thread, trivial)
// ---------------------------------------------------------------------------
__global__ void k_xform(const float* __restrict__ proj) {
    if (threadIdx.x || blockIdx.x) return;
    double Cm[3][4][4];
    for (int v = 0; v < 3; ++v) {
        double K[3][3], E[4][4];
        for (int i = 0; i < 3; ++i)
            for (int j = 0; j < 3; ++j)
                K[i][j] = (double)proj[((v*2+1)*4+i)*4+j];
        for (int i = 0; i < 4; ++i)
            for (int j = 0; j < 4; ++j)
                E[i][j] = (double)proj[((v*2+0)*4+i)*4+j];
        for (int i = 0; i < 3; ++i)
            for (int j = 0; j < 4; ++j) {
                double s = 0.0;
                for (int k = 0; k < 3; ++k) s += K[i][k]*E[k][j];
                Cm[v][i][j] = s;
            }
        for (int j = 0; j < 4; ++j) Cm[v][3][j] = E[3][j];
    }
    // Gauss-Jordan inverse of Cm[0] (double for stability)
    double A[4][8];
    for (int i = 0; i < 4; ++i)
        for (int j = 0; j < 4; ++j) { A[i][j] = Cm[0][i][j]; A[i][4+j] = (i==j) ? 1.0 : 0.0; }
    for (int col = 0; col < 4; ++col) {
        int piv = col;
        for (int r = col+1; r < 4; ++r) if (fabs(A[r][col]) > fabs(A[piv][col])) piv = r;
        if (piv != col)
            for (int j = 0; j < 8; ++j) { double t = A[col][j]; A[col][j] = A[piv][j]; A[piv][j] = t; }
        double iv = 1.0 / A[col][col];
        for (int j = 0; j < 8; ++j) A[col][j] *= iv;
        for (int r = 0; r < 4; ++r) if (r != col) {
            double f = A[r][col];
            for (int j = 0; j < 8; ++j) A[r][j] -= f * A[col][j];
        }
    }
    for (int v = 1; v < 3; ++v) {
        double M[3][4];
        for (int i = 0; i < 3; ++i)
            for (int j = 0; j < 4; ++j) {
                double s = 0.0;
                for (int k = 0; k < 4; ++k) s += Cm[v][i][k] * A[k][4+j];
                M[i][j] = s;
            }
        float* o = g_xform[v-1];
        o[0]=(float)M[0][0]; o[1]=(float)M[0][1]; o[2]=(float)M[0][2];
        o[3]=(float)M[1][0]; o[4]=(float)M[1][1]; o[5]=(float)M[1][2];
        o[6]=(float)M[2][0]; o[7]=(float)M[2][1]; o[8]=(float)M[2][2];
        o[9]=(float)M[0][3]; o[10]=(float)M[1][3]; o[11]=(float)M[2][3];
    }
}

// ---------------------------------------------------------------------------
// Kernel 2: transpose features [V,C,H,W] -> channels-last [V,H,W,C]
// ---------------------------------------------------------------------------
__global__ void k_transpose(const float* __restrict__ f) {
    int i = blockIdx.x*blockDim.x + threadIdx.x;
    if (i >= VV*HW*CC) return;
    int c  = i & (CC-1);
    int hw = (i >> 5) % HW;
    int v  = i / (HW*CC);
    g_feat_t[i] = f[((size_t)v*CC + c)*HW + hw];
}

// ---------------------------------------------------------------------------
// Kernel 3: fused homography warp + bilinear sample + variance
// One thread per voxel, all 32 channels via float4 chunks.
// ---------------------------------------------------------------------------
__global__ void __launch_bounds__(128) k_warpvar(const float* __restrict__ dvals) {
    int idx = blockIdx.x*blockDim.x + threadIdx.x;
    if (idx >= DHW) return;
    int w = idx % WW;
    int h = (idx / WW) % HH;
    float depth = dvals[idx];

    int   offs[2][4];
    float cwts[2][4];
    #pragma unroll
    for (int v = 0; v < 2; ++v) {
        const float* xf = g_xform[v];
        float x = (float)w, y = (float)h;
        float rx = xf[0]*x + xf[1]*y + xf[2];
        float ry = xf[3]*x + xf[4]*y + xf[5];
        float rz = xf[6]*x + xf[7]*y + xf[8];
        float px = rx*depth + xf[9];
        float py = ry*depth + xf[10];
        float pz = rz*depth + xf[11];
        // match reference op order: px/z/((Ws-1)/2) - 1, then re-expand
        float gx = px / pz / ((float)(WW-1)*0.5f) - 1.0f;
        float gy = py / pz / ((float)(HH-1)*0.5f) - 1.0f;
        float sx = (gx + 1.0f) * 0.5f * (float)(WW-1);
        float sy = (gy + 1.0f) * 0.5f * (float)(HH-1);
        float x0 = floorf(sx), y0 = floorf(sy);
        float x1 = x0 + 1.0f,  y1 = y0 + 1.0f;
        float wx1 = sx - x0, wx0 = 1.0f - wx1;
        float wy1 = sy - y0, wy0 = 1.0f - wy1;
        float cx[2] = {x0, x1}, cy[2] = {y0, y1};
        float wx[2] = {wx0, wx1}, wy[2] = {wy0, wy1};
        #pragma unroll
        for (int cyi = 0; cyi < 2; ++cyi)
        #pragma unroll
        for (int cxi = 0; cxi < 2; ++cxi) {
            float xi = cx[cxi], yi = cy[cyi];
            bool valid = (xi >= 0.0f) && (xi <= (float)(WW-1)) &&
                         (yi >= 0.0f) && (yi <= (float)(HH-1));
            float xc = fminf(fmaxf(xi, 0.0f), (float)(WW-1));
            float yc = fminf(fmaxf(yi, 0.0f), (float)(HH-1));
            int ii = (int)yc * WW + (int)xc;
            offs[v][cyi*2+cxi] = ii * CC;
            cwts[v][cyi*2+cxi] = wx[cxi]*wy[cyi] * (valid ? 1.0f : 0.0f);
        }
    }

    const float4* refp = (const float4*)(g_feat_t + (size_t)(h*WW + w)*CC);
    const float* s1 = g_feat_t + (size_t)HW*CC;
    const float* s2 = g_feat_t + (size_t)2*HW*CC;
    float4* outp = (float4*)(g_var + (size_t)idx*CC);

    #pragma unroll
    for (int g = 0; g < 8; ++g) {
        float4 r = refp[g];
        float sx_ = r.x, sy_ = r.y, sz_ = r.z, sw_ = r.w;
        float qx = r.x*r.x, qy = r.y*r.y, qz = r.z*r.z, qw = r.w*r.w;
        #pragma unroll
        for (int v = 0; v < 2; ++v) {
            const float* base = (v == 0) ? s1 : s2;
            float wxp = 0.f, wyp = 0.f, wzp = 0.f, wwp = 0.f;
            #pragma unroll
            for (int k = 0; k < 4; ++k) {
                float cw = cwts[v][k];
                const float4 f = *((const float4*)(base + offs[v][k]) + g);
                wxp = fmaf(cw, f.x, wxp);
                wyp = fmaf(cw, f.y, wyp);
                wzp = fmaf(cw, f.z, wzp);
                wwp = fmaf(cw, f.w, wwp);
            }
            sx_ += wxp; sy_ += wyp; sz_ += wzp; sw_ += wwp;
            qx = fmaf(wxp, wxp, qx); qy = fmaf(wyp, wyp, qy);
            qz = fmaf(wzp, wzp, qz); qw = fmaf(wwp, wwp, qw);
        }
        float4 o;
        float mx = sx_ / 3.0f, my = sy_ / 3.0f, mz = sz_ / 3.0f, mw = sw_ / 3.0f;
        o.x = qx / 3.0f - mx*mx;
        o.y = qy / 3.0f - my*my;
        o.z = qz / 3.0f - mz*mz;
        o.w = qw / 3.0f - mw*mw;
        outp[g] = o;
    }
}

// ---------------------------------------------------------------------------
// Kernels 4-6: 3x3x3 conv, channels-last, smem-tiled rolling slabs.
// STAGE 0: g_var(32) -> g_h0(8), relu
// STAGE 1: g_h0(8)  -> g_h1(8), relu
// STAGE 2: g_h1(8)  -> g_cost(1), no relu
// ---------------------------------------------------------------------------
template<int STAGE>
__global__ void __launch_bounds__(128) k_conv(const float* __restrict__ wgt,
                                              const float* __restrict__ bias) {
    constexpr int CIN   = (STAGE == 0) ? 32 : 8;
    constexpr int COUT  = (STAGE == 2) ? 1 : 8;
    constexpr bool RELU = (STAGE != 2);
    constexpr int TH = 8, TW = 16, DCHUNK = 12;
    constexpr int G = CIN / 4;
    constexpr int SLICE = (TH+2)*(TW+2)*CIN;

    const float* __restrict__ x   = (STAGE == 0) ? g_var : (STAGE == 1) ? g_h0 : g_h1;
    float*       __restrict__ out = (STAGE == 0) ? g_h0  : (STAGE == 1) ? g_h1 : g_cost;

    extern __shared__ float sm[];
    float* s_w  = sm;                        // [tap][g][co][4]
    float* slab = sm + 27*CIN*COUT;          // 3 rolling (TH+2)x(TW+2)xCIN slices

    const int tid = threadIdx.x;
    // weight gather: s_w[((tap*G+g)*COUT+co)*4+j] = wgt[(co*CIN + g*4 + j)*27 + tap]
    for (int i = tid; i < 27*CIN*COUT; i += 128) {
        int j   = i & 3;
        int co  = (i >> 2) % COUT;
        int rem = i / (4*COUT);
        int g   = rem % G;
        int tap = rem / G;
        s_w[i] = wgt[(co*CIN + g*4 + j)*27 + tap];
    }
    float bb[COUT];
    #pragma unroll
    for (int co = 0; co < COUT; ++co) bb[co] = bias[co];

    const int w0b = blockIdx.x * TW;
    const int h0b = blockIdx.y * TH;
    const int d0  = blockIdx.z * DCHUNK;
    const int tx = tid % TW, ty = tid / TW;

    auto load_slice = [&](int slot, int z) {
        float4* dst = (float4*)(slab + slot*SLICE);
        const int n = SLICE / 4;
        for (int i = tid; i < n; i += 128) {
            int g  = i % G;
            int wwi = (i / G) % (TW+2);
            int hhi = i / (G*(TW+2));
            int gh = h0b - 1 + hhi;
            int gw = w0b - 1 + wwi;
            float4 v = make_float4(0.f, 0.f, 0.f, 0.f);
            if (z >= 0 && z < DD && gh >= 0 && gh < HH && gw >= 0 && gw < WW)
                v = *(const float4*)(x + (((size_t)z*HH + gh)*WW + gw)*CIN + g*4);
            dst[i] = v;
        }
    };

    load_slice((d0-1+3) % 3, d0-1);
    load_slice((d0+3)   % 3, d0);

    for (int d = d0; d < d0 + DCHUNK; ++d) {
        load_slice((d+1+3) % 3, d+1);
        __syncthreads();

        float acc[COUT];
        #pragma unroll
        for (int co = 0; co < COUT; ++co) acc[co] = bb[co];

        for (int kd = 0; kd < 3; ++kd) {
            const float* sl = slab + ((d-1+kd+3) % 3)*SLICE;
            for (int kh = 0; kh < 3; ++kh)
            for (int kw = 0; kw < 3; ++kw) {
                const int tap = (kd*3+kh)*3 + kw;
                const float4* xp = (const float4*)(sl + ((ty+kh)*(TW+2) + (tx+kw))*CIN);
                const float4* wp = (const float4*)(s_w + tap*G*COUT*4);
                #pragma unroll
                for (int g = 0; g < G; ++g) {
                    float4 xv = xp[g];
                    #pragma unroll
                    for (int co = 0; co < COUT; ++co) {
                        float4 wv = wp[g*COUT + co];
                        acc[co] = fmaf(xv.x, wv.x, acc[co]);
                        acc[co] = fmaf(xv.y, wv.y, acc[co]);
                        acc[co] = fmaf(xv.z, wv.z, acc[co]);
                        acc[co] = fmaf(xv.w, wv.w, acc[co]);
                    }
                }
            }
        }

        float* op = out + (((size_t)d*HH + (h0b+ty))*WW + (w0b+tx))*COUT;
        if constexpr (COUT == 8) {
            float4 o0, o1;
            o0.x = RELU ? fmaxf(acc[0], 0.f) : acc[0];
            o0.y = RELU ? fmaxf(acc[1], 0.f) : acc[1];
            o0.z = RELU ? fmaxf(acc[2], 0.f) : acc[2];
            o0.w = RELU ? fmaxf(acc[3], 0.f) : acc[3];
            o1.x = RELU ? fmaxf(acc[4], 0.f) : acc[4];
            o1.y = RELU ? fmaxf(acc[5], 0.f) : acc[5];
            o1.z = RELU ? fmaxf(acc[6], 0.f) : acc[6];
            o1.w = RELU ? fmaxf(acc[7], 0.f) : acc[7];
            ((float4*)op)[0] = o0;
            ((float4*)op)[1] = o1;
        } else {
            float a = acc[0];
            if (RELU) a = fmaxf(a, 0.f);
            op[0] = a;
        }
        __syncthreads();
    }
}

// ---------------------------------------------------------------------------
// Kernel 7: softmax over D + expected depth + 4-tap confidence
// ---------------------------------------------------------------------------
__global__ void k_softmax(const float* __restrict__ dvals, float* __restrict__ out) {
    int p = blockIdx.x*blockDim.x + threadIdx.x;
    if (p >= HW) return;
    float c[DD];
    float m = -1e30f;
    #pragma unroll
    for (int d = 0; d < DD; ++d) { c[d] = g_cost[(size_t)d*HW + p]; m = fmaxf(m, c[d]); }
    float S = 0.f;
    #pragma unroll
    for (int d = 0; d < DD; ++d) { c[d] = expf(c[d] - m); S += c[d]; }
    float inv = 1.0f / S;
    float depth = 0.f, fid = 0.f;
    #pragma unroll
    for (int d = 0; d < DD; ++d) {
        float pr = c[d] * inv;
        depth = fmaf(pr, dvals[(size_t)d*HW + p], depth);
        fid   = fmaf(pr, (float)d, fid);
    }
    int di = (int)fid;                 // truncation (>=0), matches astype(int32)
    di = max(0, min(DD-1, di));
    float conf = 0.f;
    #pragma unroll
    for (int d = 0; d < DD; ++d)
        if (d >= di-1 && d <= di+2) conf += c[d] * inv;
    out[p]      = depth;
    out[HW + p] = conf;
}

// ---------------------------------------------------------------------------
// Launch
// ---------------------------------------------------------------------------
extern "C" void kernel_launch(void* const* d_in, const int* in_sizes, int n_in,
                              void* d_out, int out_size) {
    const float* features = (const float*)d_in[0];
    const float* proj     = (const float*)d_in[1];
    const float* dvals    = (const float*)d_in[2];
    const float* w0 = (const float*)d_in[3];
    const float* b0 = (const float*)d_in[4];
    const float* w1 = (const float*)d_in[5];
    const float* b1 = (const float*)d_in[6];
    const float* w2 = (const float*)d_in[7];
    const float* b2 = (const float*)d_in[8];
    float* out = (float*)d_out;

    const int smem0 = (27*32*8 + 3*10*18*32) * 4;   // 96768 B
    const int smem1 = (27*8*8  + 3*10*18*8 ) * 4;   // 24192 B
    const int smem2 = (27*8*1  + 3*10*18*8 ) * 4;   // 18144 B
    cudaFuncSetAttribute(k_conv<0>, cudaFuncAttributeMaxDynamicSharedMemorySize, smem0);
    cudaFuncSetAttribute(k_conv<1>, cudaFuncAttributeMaxDynamicSharedMemorySize, smem1);
    cudaFuncSetAttribute(k_conv<2>, cudaFuncAttributeMaxDynamicSharedMemorySize, smem2);

    k_xform<<<1, 1>>>(proj);
    k_transpose<<<(VV*HW*CC + 255)/256, 256>>>(features);
    k_warpvar<<<(DHW + 127)/128, 128>>>(dvals);

    dim3 cgrid(WW/16, HH/8, DD/12);   // (10, 16, 4)
    k_conv<0><<<cgrid, 128, smem0>>>(w0, b0);
    k_conv<1><<<cgrid, 128, smem1>>>(w1, b1);
    k_conv<2><<<cgrid, 128, smem2>>>(w2, b2);

    k_softmax<<<(HW + 255)/256, 256>>>(dvals, out);
}

// round 2
// speedup vs baseline: 1.9091x; 1.9091x over previous
#include <cuda_runtime.h>
#include <math.h>

#define VV 3
#define CC 32
#define DD 48
#define HH 128
#define WW 160
#define HW (HH*WW)        /* 20480 */
#define DHW (DD*HW)       /* 983040 */

// ---------------------------------------------------------------------------
// Scratch
// ---------------------------------------------------------------------------
__device__ float g_xform[2][12];
__device__ float g_feat_t[(size_t)VV*HW*CC];     // channels-last features
__device__ float g_var[(size_t)DHW*CC];          // variance volume [D,H,W,32]
__device__ float g_h0[(size_t)DHW*8];            // conv0 out [D,H,W,8]
__device__ float g_h1[(size_t)DHW*8];            // conv1 out [D,H,W,8]
__device__ float g_cost[(size_t)DHW];            // conv2 out [D,H,W]

// packed fp32 helpers (Blackwell f32x2)
__device__ __forceinline__ void fma2(unsigned long long& d,
                                     unsigned long long a,
                                     unsigned long long b) {
    asm("fma.rn.f32x2 %0, %1, %2, %0;" : "+l"(d) : "l"(a), "l"(b));
}
__device__ __forceinline__ float unpack_sum(unsigned long long v) {
    float lo, hi;
    asm("mov.b64 {%0, %1}, %2;" : "=f"(lo), "=f"(hi) : "l"(v));
    return lo + hi;
}

// ---------------------------------------------------------------------------
// Kernel 1: projective transforms  M_v = C_v * inv(C_0)
// ---------------------------------------------------------------------------
__global__ void k_xform(const float* __restrict__ proj) {
    if (threadIdx.x || blockIdx.x) return;
    double Cm[3][4][4];
    for (int v = 0; v < 3; ++v) {
        double K[3][3], E[4][4];
        for (int i = 0; i < 3; ++i)
            for (int j = 0; j < 3; ++j)
                K[i][j] = (double)proj[((v*2+1)*4+i)*4+j];
        for (int i = 0; i < 4; ++i)
            for (int j = 0; j < 4; ++j)
                E[i][j] = (double)proj[((v*2+0)*4+i)*4+j];
        for (int i = 0; i < 3; ++i)
            for (int j = 0; j < 4; ++j) {
                double s = 0.0;
                for (int k = 0; k < 3; ++k) s += K[i][k]*E[k][j];
                Cm[v][i][j] = s;
            }
        for (int j = 0; j < 4; ++j) Cm[v][3][j] = E[3][j];
    }
    double A[4][8];
    for (int i = 0; i < 4; ++i)
        for (int j = 0; j < 4; ++j) { A[i][j] = Cm[0][i][j]; A[i][4+j] = (i==j) ? 1.0 : 0.0; }
    for (int col = 0; col < 4; ++col) {
        int piv = col;
        for (int r = col+1; r < 4; ++r) if (fabs(A[r][col]) > fabs(A[piv][col])) piv = r;
        if (piv != col)
            for (int j = 0; j < 8; ++j) { double t = A[col][j]; A[col][j] = A[piv][j]; A[piv][j] = t; }
        double iv = 1.0 / A[col][col];
        for (int j = 0; j < 8; ++j) A[col][j] *= iv;
        for (int r = 0; r < 4; ++r) if (r != col) {
            double f = A[r][col];
            for (int j = 0; j < 8; ++j) A[r][j] -= f * A[col][j];
        }
    }
    for (int v = 1; v < 3; ++v) {
        double M[3][4];
        for (int i = 0; i < 3; ++i)
            for (int j = 0; j < 4; ++j) {
                double s = 0.0;
                for (int k = 0; k < 4; ++k) s += Cm[v][i][k] * A[k][4+j];
                M[i][j] = s;
            }
        float* o = g_xform[v-1];
        o[0]=(float)M[0][0]; o[1]=(float)M[0][1]; o[2]=(float)M[0][2];
        o[3]=(float)M[1][0]; o[4]=(float)M[1][1]; o[5]=(float)M[1][2];
        o[6]=(float)M[2][0]; o[7]=(float)M[2][1]; o[8]=(float)M[2][2];
        o[9]=(float)M[0][3]; o[10]=(float)M[1][3]; o[11]=(float)M[2][3];
    }
}

// ---------------------------------------------------------------------------
// Kernel 2: transpose features [V,C,H,W] -> [V,H,W,C]
// ---------------------------------------------------------------------------
__global__ void k_transpose(const float* __restrict__ f) {
    int i = blockIdx.x*blockDim.x + threadIdx.x;
    if (i >= VV*HW*CC) return;
    int c  = i & (CC-1);
    int hw = (i >> 5) % HW;
    int v  = i / (HW*CC);
    g_feat_t[i] = f[((size_t)v*CC + c)*HW + hw];
}

// ---------------------------------------------------------------------------
// Kernel 3: fused homography warp + bilinear sample + variance
// ---------------------------------------------------------------------------
__global__ void __launch_bounds__(128) k_warpvar(const float* __restrict__ dvals) {
    int idx = blockIdx.x*blockDim.x + threadIdx.x;
    if (idx >= DHW) return;
    int w = idx % WW;
    int h = (idx / WW) % HH;
    float depth = dvals[idx];

    int   offs[2][4];
    float cwts[2][4];
    #pragma unroll
    for (int v = 0; v < 2; ++v) {
        const float* xf = g_xform[v];
        float x = (float)w, y = (float)h;
        float rx = xf[0]*x + xf[1]*y + xf[2];
        float ry = xf[3]*x + xf[4]*y + xf[5];
        float rz = xf[6]*x + xf[7]*y + xf[8];
        float px = rx*depth + xf[9];
        float py = ry*depth + xf[10];
        float pz = rz*depth + xf[11];
        float gx = px / pz / ((float)(WW-1)*0.5f) - 1.0f;
        float gy = py / pz / ((float)(HH-1)*0.5f) - 1.0f;
        float sx = (gx + 1.0f) * 0.5f * (float)(WW-1);
        float sy = (gy + 1.0f) * 0.5f * (float)(HH-1);
        float x0 = floorf(sx), y0 = floorf(sy);
        float wx1 = sx - x0, wx0 = 1.0f - wx1;
        float wy1 = sy - y0, wy0 = 1.0f - wy1;
        float cx[2] = {x0, x0+1.0f}, cy[2] = {y0, y0+1.0f};
        float wx[2] = {wx0, wx1}, wy[2] = {wy0, wy1};
        #pragma unroll
        for (int cyi = 0; cyi < 2; ++cyi)
        #pragma unroll
        for (int cxi = 0; cxi < 2; ++cxi) {
            float xi = cx[cxi], yi = cy[cyi];
            bool valid = (xi >= 0.0f) && (xi <= (float)(WW-1)) &&
                         (yi >= 0.0f) && (yi <= (float)(HH-1));
            float xc = fminf(fmaxf(xi, 0.0f), (float)(WW-1));
            float yc = fminf(fmaxf(yi, 0.0f), (float)(HH-1));
            int ii = (int)yc * WW + (int)xc;
            offs[v][cyi*2+cxi] = ii * CC;
            cwts[v][cyi*2+cxi] = wx[cxi]*wy[cyi] * (valid ? 1.0f : 0.0f);
        }
    }

    const float4* refp = (const float4*)(g_feat_t + (size_t)(h*WW + w)*CC);
    const float* s1 = g_feat_t + (size_t)HW*CC;
    const float* s2 = g_feat_t + (size_t)2*HW*CC;
    float4* outp = (float4*)(g_var + (size_t)idx*CC);

    #pragma unroll
    for (int g = 0; g < 8; ++g) {
        float4 r = refp[g];
        float sx_ = r.x, sy_ = r.y, sz_ = r.z, sw_ = r.w;
        float qx = r.x*r.x, qy = r.y*r.y, qz = r.z*r.z, qw = r.w*r.w;
        #pragma unroll
        for (int v = 0; v < 2; ++v) {
            const float* base = (v == 0) ? s1 : s2;
            float wxp = 0.f, wyp = 0.f, wzp = 0.f, wwp = 0.f;
            #pragma unroll
            for (int k = 0; k < 4; ++k) {
                float cw = cwts[v][k];
                const float4 f = *((const float4*)(base + offs[v][k]) + g);
                wxp = fmaf(cw, f.x, wxp);
                wyp = fmaf(cw, f.y, wyp);
                wzp = fmaf(cw, f.z, wzp);
                wwp = fmaf(cw, f.w, wwp);
            }
            sx_ += wxp; sy_ += wyp; sz_ += wzp; sw_ += wwp;
            qx = fmaf(wxp, wxp, qx); qy = fmaf(wyp, wyp, qy);
            qz = fmaf(wzp, wzp, qz); qw = fmaf(wwp, wwp, qw);
        }
        float4 o;
        float mx = sx_ / 3.0f, my = sy_ / 3.0f, mz = sz_ / 3.0f, mw = sw_ / 3.0f;
        o.x = qx / 3.0f - mx*mx;
        o.y = qy / 3.0f - my*my;
        o.z = qz / 3.0f - mz*mz;
        o.w = qw / 3.0f - mw*mw;
        outp[g] = o;
    }
}

// ---------------------------------------------------------------------------
// Kernels 4-6: 3x3x3 conv with D-strip register blocking + packed f32x2 FMA.
// Each thread owns one (h,w) and DS=6 consecutive depth outputs x COUT couts.
// Channel pairs (c,c+1) ride in the two lanes of f32x2; halves summed at end.
// Block: 8x16 spatial tile, 128 threads, 8 slices (d0-1..d0+6) in smem.
// ---------------------------------------------------------------------------
template<int STAGE>
__global__ void __launch_bounds__(128, 1) k_conv(const float* __restrict__ wgt,
                                                 const float* __restrict__ bias) {
    constexpr int CIN   = (STAGE == 0) ? 32 : 8;
    constexpr int COUT  = (STAGE == 2) ? 1 : 8;
    constexpr bool RELU = (STAGE != 2);
    constexpr int TH = 8, TW = 16, DS = 6, NSL = DS + 2;
    constexpr int G = CIN / 4;
    constexpr int SLICE = (TH+2)*(TW+2)*CIN;     // floats per slice

    const float* __restrict__ x   = (STAGE == 0) ? g_var : (STAGE == 1) ? g_h0 : g_h1;
    float*       __restrict__ out = (STAGE == 0) ? g_h0  : (STAGE == 1) ? g_h1 : g_cost;

    extern __shared__ float sm[];
    float* s_w  = sm;                            // [tap][g][co][4]
    float* slab = sm + 27*CIN*COUT;              // NSL slices

    const int tid = threadIdx.x;
    const int tx = tid % TW, ty = tid / TW;
    const int w0 = blockIdx.x * TW;
    const int h0 = blockIdx.y * TH;
    const int d0 = blockIdx.z * DS;

    // weights: s_w[((tap*G+g)*COUT+co)*4+j] = wgt[(co*CIN + g*4 + j)*27 + tap]
    for (int i = tid; i < 27*CIN*COUT; i += 128) {
        int j   = i & 3;
        int co  = (i >> 2) % COUT;
        int rem = i / (4*COUT);
        int g   = rem % G;
        int tap = rem / G;
        s_w[i] = wgt[(co*CIN + g*4 + j)*27 + tap];
    }

    // load NSL slices (zero-padded halo)
    {
        const int NTOT = NSL * SLICE / 4;
        float4* dst = (float4*)slab;
        for (int i = tid; i < NTOT; i += 128) {
            int g   = i % G;
            int col = (i / G) % (TW+2);
            int rem = i / (G*(TW+2));
            int row = rem % (TH+2);
            int s   = rem / (TH+2);
            int z  = d0 - 1 + s;
            int gh = h0 - 1 + row;
            int gw = w0 - 1 + col;
            float4 v = make_float4(0.f, 0.f, 0.f, 0.f);
            if (z >= 0 && z < DD && gh >= 0 && gh < HH && gw >= 0 && gw < WW)
                v = *(const float4*)(x + (((size_t)z*HH + gh)*WW + gw)*CIN + g*4);
            dst[i] = v;
        }
    }
    __syncthreads();

    unsigned long long acc[DS][COUT];
    #pragma unroll
    for (int o = 0; o < DS; ++o)
        #pragma unroll
        for (int co = 0; co < COUT; ++co) acc[o][co] = 0ull;

    #pragma unroll 1
    for (int kh = 0; kh < 3; ++kh) {
        #pragma unroll 1
        for (int kw = 0; kw < 3; ++kw) {
            const float* xb = slab + ((ty+kh)*(TW+2) + (tx+kw))*CIN;
            const float* wb = s_w + (kh*3 + kw)*G*COUT*4;
            #pragma unroll 2
            for (int g = 0; g < G; ++g) {
                ulonglong2 xv[NSL];
                #pragma unroll
                for (int s = 0; s < NSL; ++s)
                    xv[s] = *(const ulonglong2*)(xb + s*SLICE + g*4);
                #pragma unroll
                for (int kd = 0; kd < 3; ++kd) {
                    const ulonglong2* wp =
                        (const ulonglong2*)(wb + kd*9*G*COUT*4 + g*COUT*4);
                    ulonglong2 wv[COUT];
                    #pragma unroll
                    for (int co = 0; co < COUT; ++co) wv[co] = wp[co];
                    #pragma unroll
                    for (int o = 0; o < DS; ++o) {
                        #pragma unroll
                        for (int co = 0; co < COUT; ++co) {
                            fma2(acc[o][co], xv[o+kd].x, wv[co].x);
                            fma2(acc[o][co], xv[o+kd].y, wv[co].y);
                        }
                    }
                }
            }
        }
    }

    float bb[COUT];
    #pragma unroll
    for (int co = 0; co < COUT; ++co) bb[co] = bias[co];

    #pragma unroll
    for (int o = 0; o < DS; ++o) {
        int d = d0 + o;
        float* op = out + (((size_t)d*HH + (h0+ty))*WW + (w0+tx))*COUT;
        if constexpr (COUT == 8) {
            float r[8];
            #pragma unroll
            for (int co = 0; co < 8; ++co) {
                float v = unpack_sum(acc[o][co]) + bb[co];
                r[co] = RELU ? fmaxf(v, 0.f) : v;
            }
            ((float4*)op)[0] = make_float4(r[0], r[1], r[2], r[3]);
            ((float4*)op)[1] = make_float4(r[4], r[5], r[6], r[7]);
        } else {
            float v = unpack_sum(acc[o][0]) + bb[0];
            op[0] = RELU ? fmaxf(v, 0.f) : v;
        }
    }
}

// ---------------------------------------------------------------------------
// Kernel 7: softmax over D + expected depth + 4-tap confidence
// ---------------------------------------------------------------------------
__global__ void k_softmax(const float* __restrict__ dvals, float* __restrict__ out) {
    int p = blockIdx.x*blockDim.x + threadIdx.x;
    if (p >= HW) return;
    float c[DD];
    float m = -1e30f;
    #pragma unroll
    for (int d = 0; d < DD; ++d) { c[d] = g_cost[(size_t)d*HW + p]; m = fmaxf(m, c[d]); }
    float S = 0.f;
    #pragma unroll
    for (int d = 0; d < DD; ++d) { c[d] = expf(c[d] - m); S += c[d]; }
    float inv = 1.0f / S;
    float depth = 0.f, fid = 0.f;
    #pragma unroll
    for (int d = 0; d < DD; ++d) {
        float pr = c[d] * inv;
        depth = fmaf(pr, dvals[(size_t)d*HW + p], depth);
        fid   = fmaf(pr, (float)d, fid);
    }
    int di = (int)fid;
    di = max(0, min(DD-1, di));
    float conf = 0.f;
    #pragma unroll
    for (int d = 0; d < DD; ++d)
        if (d >= di-1 && d <= di+2) conf += c[d] * inv;
    out[p]      = depth;
    out[HW + p] = conf;
}

// ---------------------------------------------------------------------------
// Launch
// ---------------------------------------------------------------------------
extern "C" void kernel_launch(void* const* d_in, const int* in_sizes, int n_in,
                              void* d_out, int out_size) {
    const float* features = (const float*)d_in[0];
    const float* proj     = (const float*)d_in[1];
    const float* dvals    = (const float*)d_in[2];
    const float* w0 = (const float*)d_in[3];
    const float* b0 = (const float*)d_in[4];
    const float* w1 = (const float*)d_in[5];
    const float* b1 = (const float*)d_in[6];
    const float* w2 = (const float*)d_in[7];
    const float* b2 = (const float*)d_in[8];
    float* out = (float*)d_out;

    // smem: weights + 8 slices of (10*18*CIN) floats
    const int smem0 = (27*32*8 + 8*10*18*32) * 4;   // 27648 + 184320 = 211968 B
    const int smem1 = (27*8*8  + 8*10*18*8 ) * 4;   //  6912 +  46080 =  52992 B
    const int smem2 = (27*8*1  + 8*10*18*8 ) * 4;   //   864 +  46080 =  46944 B
    cudaFuncSetAttribute(k_conv<0>, cudaFuncAttributeMaxDynamicSharedMemorySize, smem0);
    cudaFuncSetAttribute(k_conv<1>, cudaFuncAttributeMaxDynamicSharedMemorySize, smem1);
    cudaFuncSetAttribute(k_conv<2>, cudaFuncAttributeMaxDynamicSharedMemorySize, smem2);

    k_xform<<<1, 1>>>(proj);
    k_transpose<<<(VV*HW*CC + 255)/256, 256>>>(features);
    k_warpvar<<<(DHW + 127)/128, 128>>>(dvals);

    dim3 cgrid(WW/16, HH/8, DD/6);   // (10, 16, 8)
    k_conv<0><<<cgrid, 128, smem0>>>(w0, b0);
    k_conv<1><<<cgrid, 128, smem1>>>(w1, b1);
    k_conv<2><<<cgrid, 128, smem2>>>(w2, b2);

    k_softmax<<<(HW + 255)/256, 256>>>(dvals, out);
}

// round 3
// speedup vs baseline: 2.1475x; 1.1249x over previous
#include <cuda_runtime.h>
#include <math.h>

#define VV 3
#define CC 32
#define DD 48
#define HH 128
#define WW 160
#define HW (HH*WW)        /* 20480 */
#define DHW (DD*HW)       /* 983040 */

// ---------------------------------------------------------------------------
// Scratch
// ---------------------------------------------------------------------------
__device__ float g_xform[2][12];
__device__ float g_feat_t[(size_t)VV*HW*CC];     // channels-last features
__device__ float g_var[(size_t)DHW*CC];          // variance volume [D,H,W,32]
__device__ float g_h0[(size_t)DHW*8];            // conv0 out [D,H,W,8]
__device__ float g_h1[(size_t)DHW*8];            // conv1 out [D,H,W,8]
__device__ float g_cost[(size_t)DHW];            // conv2 out [D,H,W]

// packed fp32 helpers (Blackwell f32x2)
__device__ __forceinline__ void fma2(unsigned long long& d,
                                     unsigned long long a,
                                     unsigned long long b) {
    asm("fma.rn.f32x2 %0, %1, %2, %0;" : "+l"(d) : "l"(a), "l"(b));
}
__device__ __forceinline__ float unpack_sum(unsigned long long v) {
    float lo, hi;
    asm("mov.b64 {%0, %1}, %2;" : "=f"(lo), "=f"(hi) : "l"(v));
    return lo + hi;
}

// ---------------------------------------------------------------------------
// Kernel 1: projective transforms  M_v = C_v * inv(C_0)
// ---------------------------------------------------------------------------
__global__ void k_xform(const float* __restrict__ proj) {
    if (threadIdx.x || blockIdx.x) return;
    double Cm[3][4][4];
    for (int v = 0; v < 3; ++v) {
        double K[3][3], E[4][4];
        for (int i = 0; i < 3; ++i)
            for (int j = 0; j < 3; ++j)
                K[i][j] = (double)proj[((v*2+1)*4+i)*4+j];
        for (int i = 0; i < 4; ++i)
            for (int j = 0; j < 4; ++j)
                E[i][j] = (double)proj[((v*2+0)*4+i)*4+j];
        for (int i = 0; i < 3; ++i)
            for (int j = 0; j < 4; ++j) {
                double s = 0.0;
                for (int k = 0; k < 3; ++k) s += K[i][k]*E[k][j];
                Cm[v][i][j] = s;
            }
        for (int j = 0; j < 4; ++j) Cm[v][3][j] = E[3][j];
    }
    double A[4][8];
    for (int i = 0; i < 4; ++i)
        for (int j = 0; j < 4; ++j) { A[i][j] = Cm[0][i][j]; A[i][4+j] = (i==j) ? 1.0 : 0.0; }
    for (int col = 0; col < 4; ++col) {
        int piv = col;
        for (int r = col+1; r < 4; ++r) if (fabs(A[r][col]) > fabs(A[piv][col])) piv = r;
        if (piv != col)
            for (int j = 0; j < 8; ++j) { double t = A[col][j]; A[col][j] = A[piv][j]; A[piv][j] = t; }
        double iv = 1.0 / A[col][col];
        for (int j = 0; j < 8; ++j) A[col][j] *= iv;
        for (int r = 0; r < 4; ++r) if (r != col) {
            double f = A[r][col];
            for (int j = 0; j < 8; ++j) A[r][j] -= f * A[col][j];
        }
    }
    for (int v = 1; v < 3; ++v) {
        double M[3][4];
        for (int i = 0; i < 3; ++i)
            for (int j = 0; j < 4; ++j) {
                double s = 0.0;
                for (int k = 0; k < 4; ++k) s += Cm[v][i][k] * A[k][4+j];
                M[i][j] = s;
            }
        float* o = g_xform[v-1];
        o[0]=(float)M[0][0]; o[1]=(float)M[0][1]; o[2]=(float)M[0][2];
        o[3]=(float)M[1][0]; o[4]=(float)M[1][1]; o[5]=(float)M[1][2];
        o[6]=(float)M[2][0]; o[7]=(float)M[2][1]; o[8]=(float)M[2][2];
        o[9]=(float)M[0][3]; o[10]=(float)M[1][3]; o[11]=(float)M[2][3];
    }
}

// ---------------------------------------------------------------------------
// Kernel 2: transpose features [V,C,H,W] -> [V,H,W,C]
// ---------------------------------------------------------------------------
__global__ void k_transpose(const float* __restrict__ f) {
    int i = blockIdx.x*blockDim.x + threadIdx.x;
    if (i >= VV*HW*CC) return;
    int c  = i & (CC-1);
    int hw = (i >> 5) % HW;
    int v  = i / (HW*CC);
    g_feat_t[i] = f[((size_t)v*CC + c)*HW + hw];
}

// ---------------------------------------------------------------------------
// Kernel 3: fused homography warp + bilinear sample + variance
// ---------------------------------------------------------------------------
__global__ void __launch_bounds__(128) k_warpvar(const float* __restrict__ dvals) {
    int idx = blockIdx.x*blockDim.x + threadIdx.x;
    if (idx >= DHW) return;
    int w = idx % WW;
    int h = (idx / WW) % HH;
    float depth = dvals[idx];

    int   offs[2][4];
    float cwts[2][4];
    #pragma unroll
    for (int v = 0; v < 2; ++v) {
        const float* xf = g_xform[v];
        float x = (float)w, y = (float)h;
        float rx = xf[0]*x + xf[1]*y + xf[2];
        float ry = xf[3]*x + xf[4]*y + xf[5];
        float rz = xf[6]*x + xf[7]*y + xf[8];
        float px = rx*depth + xf[9];
        float py = ry*depth + xf[10];
        float pz = rz*depth + xf[11];
        float gx = px / pz / ((float)(WW-1)*0.5f) - 1.0f;
        float gy = py / pz / ((float)(HH-1)*0.5f) - 1.0f;
        float sx = (gx + 1.0f) * 0.5f * (float)(WW-1);
        float sy = (gy + 1.0f) * 0.5f * (float)(HH-1);
        float x0 = floorf(sx), y0 = floorf(sy);
        float wx1 = sx - x0, wx0 = 1.0f - wx1;
        float wy1 = sy - y0, wy0 = 1.0f - wy1;
        float cx[2] = {x0, x0+1.0f}, cy[2] = {y0, y0+1.0f};
        float wx[2] = {wx0, wx1}, wy[2] = {wy0, wy1};
        #pragma unroll
        for (int cyi = 0; cyi < 2; ++cyi)
        #pragma unroll
        for (int cxi = 0; cxi < 2; ++cxi) {
            float xi = cx[cxi], yi = cy[cyi];
            bool valid = (xi >= 0.0f) && (xi <= (float)(WW-1)) &&
                         (yi >= 0.0f) && (yi <= (float)(HH-1));
            float xc = fminf(fmaxf(xi, 0.0f), (float)(WW-1));
            float yc = fminf(fmaxf(yi, 0.0f), (float)(HH-1));
            int ii = (int)yc * WW + (int)xc;
            offs[v][cyi*2+cxi] = ii * CC;
            cwts[v][cyi*2+cxi] = wx[cxi]*wy[cyi] * (valid ? 1.0f : 0.0f);
        }
    }

    const float4* refp = (const float4*)(g_feat_t + (size_t)(h*WW + w)*CC);
    const float* s1 = g_feat_t + (size_t)HW*CC;
    const float* s2 = g_feat_t + (size_t)2*HW*CC;
    float4* outp = (float4*)(g_var + (size_t)idx*CC);

    #pragma unroll
    for (int g = 0; g < 8; ++g) {
        float4 r = refp[g];
        float sx_ = r.x, sy_ = r.y, sz_ = r.z, sw_ = r.w;
        float qx = r.x*r.x, qy = r.y*r.y, qz = r.z*r.z, qw = r.w*r.w;
        #pragma unroll
        for (int v = 0; v < 2; ++v) {
            const float* base = (v == 0) ? s1 : s2;
            float wxp = 0.f, wyp = 0.f, wzp = 0.f, wwp = 0.f;
            #pragma unroll
            for (int k = 0; k < 4; ++k) {
                float cw = cwts[v][k];
                const float4 f = *((const float4*)(base + offs[v][k]) + g);
                wxp = fmaf(cw, f.x, wxp);
                wyp = fmaf(cw, f.y, wyp);
                wzp = fmaf(cw, f.z, wzp);
                wwp = fmaf(cw, f.w, wwp);
            }
            sx_ += wxp; sy_ += wyp; sz_ += wzp; sw_ += wwp;
            qx = fmaf(wxp, wxp, qx); qy = fmaf(wyp, wyp, qy);
            qz = fmaf(wzp, wzp, qz); qw = fmaf(wwp, wwp, qw);
        }
        float4 o;
        float mx = sx_ / 3.0f, my = sy_ / 3.0f, mz = sz_ / 3.0f, mw = sw_ / 3.0f;
        o.x = qx / 3.0f - mx*mx;
        o.y = qy / 3.0f - my*my;
        o.z = qz / 3.0f - mz*mz;
        o.w = qw / 3.0f - mw*mw;
        outp[g] = o;
    }
}

// ---------------------------------------------------------------------------
// Kernels 4-6: 3x3x3 conv, D-strip register blocking, packed f32x2 FMA,
// and PADDED smem pixel stride (CIN+4) to kill bank conflicts:
// lane stride = 36 (or 12) floats == 4 mod 32 banks -> conflict-free LDS.128.
// ---------------------------------------------------------------------------
template<int STAGE>
__global__ void __launch_bounds__(128, (STAGE == 0) ? 1 : 2)
k_conv(const float* __restrict__ wgt, const float* __restrict__ bias) {
    constexpr int CIN   = (STAGE == 0) ? 32 : 8;
    constexpr int COUT  = (STAGE == 2) ? 1 : 8;
    constexpr bool RELU = (STAGE != 2);
    constexpr int TH = 8, TW = 16;
    constexpr int DS  = (STAGE == 0) ? 4 : 6;
    constexpr int NSL = DS + 2;
    constexpr int G = CIN / 4;
    constexpr int PS = CIN + 4;                  // padded pixel stride (floats)
    constexpr int SLICE = (TH+2)*(TW+2)*PS;      // floats per padded slice

    const float* __restrict__ x   = (STAGE == 0) ? g_var : (STAGE == 1) ? g_h0 : g_h1;
    float*       __restrict__ out = (STAGE == 0) ? g_h0  : (STAGE == 1) ? g_h1 : g_cost;

    extern __shared__ float sm[];
    float* s_w  = sm;                            // [tap][g][co][4]
    float* slab = sm + 27*CIN*COUT;              // NSL padded slices

    const int tid = threadIdx.x;
    const int tx = tid % TW, ty = tid / TW;
    const int w0 = blockIdx.x * TW;
    const int h0 = blockIdx.y * TH;
    const int d0 = blockIdx.z * DS;

    // weights: s_w[((tap*G+g)*COUT+co)*4+j] = wgt[(co*CIN + g*4 + j)*27 + tap]
    for (int i = tid; i < 27*CIN*COUT; i += 128) {
        int j   = i & 3;
        int co  = (i >> 2) % COUT;
        int rem = i / (4*COUT);
        int g   = rem % G;
        int tap = rem / G;
        s_w[i] = wgt[(co*CIN + g*4 + j)*27 + tap];
    }

    // load NSL slices (zero-padded halo), padded stride
    {
        const int NTOT = NSL * (TH+2)*(TW+2) * G;
        for (int i = tid; i < NTOT; i += 128) {
            int g   = i % G;
            int col = (i / G) % (TW+2);
            int rem = i / (G*(TW+2));
            int row = rem % (TH+2);
            int s   = rem / (TH+2);
            int z  = d0 - 1 + s;
            int gh = h0 - 1 + row;
            int gw = w0 - 1 + col;
            float4 v = make_float4(0.f, 0.f, 0.f, 0.f);
            if (z >= 0 && z < DD && gh >= 0 && gh < HH && gw >= 0 && gw < WW)
                v = *(const float4*)(x + (((size_t)z*HH + gh)*WW + gw)*CIN + g*4);
            *(float4*)(slab + ((s*(TH+2) + row)*(TW+2) + col)*PS + g*4) = v;
        }
    }
    __syncthreads();

    unsigned long long acc[DS][COUT];
    #pragma unroll
    for (int o = 0; o < DS; ++o)
        #pragma unroll
        for (int co = 0; co < COUT; ++co) acc[o][co] = 0ull;

    #pragma unroll 1
    for (int kh = 0; kh < 3; ++kh) {
        #pragma unroll 1
        for (int kw = 0; kw < 3; ++kw) {
            const float* xb = slab + ((ty+kh)*(TW+2) + (tx+kw))*PS;
            const float* wb = s_w + (kh*3 + kw)*G*COUT*4;
            #pragma unroll 2
            for (int g = 0; g < G; ++g) {
                ulonglong2 xv[NSL];
                #pragma unroll
                for (int s = 0; s < NSL; ++s)
                    xv[s] = *(const ulonglong2*)(xb + s*SLICE + g*4);
                #pragma unroll
                for (int kd = 0; kd < 3; ++kd) {
                    const ulonglong2* wp =
                        (const ulonglong2*)(wb + kd*9*G*COUT*4 + g*COUT*4);
                    ulonglong2 wv[COUT];
                    #pragma unroll
                    for (int co = 0; co < COUT; ++co) wv[co] = wp[co];
                    #pragma unroll
                    for (int o = 0; o < DS; ++o) {
                        #pragma unroll
                        for (int co = 0; co < COUT; ++co) {
                            fma2(acc[o][co], xv[o+kd].x, wv[co].x);
                            fma2(acc[o][co], xv[o+kd].y, wv[co].y);
                        }
                    }
                }
            }
        }
    }

    float bb[COUT];
    #pragma unroll
    for (int co = 0; co < COUT; ++co) bb[co] = bias[co];

    #pragma unroll
    for (int o = 0; o < DS; ++o) {
        int d = d0 + o;
        float* op = out + (((size_t)d*HH + (h0+ty))*WW + (w0+tx))*COUT;
        if constexpr (COUT == 8) {
            float r[8];
            #pragma unroll
            for (int co = 0; co < 8; ++co) {
                float v = unpack_sum(acc[o][co]) + bb[co];
                r[co] = RELU ? fmaxf(v, 0.f) : v;
            }
            ((float4*)op)[0] = make_float4(r[0], r[1], r[2], r[3]);
            ((float4*)op)[1] = make_float4(r[4], r[5], r[6], r[7]);
        } else {
            float v = unpack_sum(acc[o][0]) + bb[0];
            op[0] = RELU ? fmaxf(v, 0.f) : v;
        }
    }
}

// ---------------------------------------------------------------------------
// Kernel 7: softmax over D + expected depth + 4-tap confidence
// ---------------------------------------------------------------------------
__global__ void k_softmax(const float* __restrict__ dvals, float* __restrict__ out) {
    int p = blockIdx.x*blockDim.x + threadIdx.x;
    if (p >= HW) return;
    float c[DD];
    float m = -1e30f;
    #pragma unroll
    for (int d = 0; d < DD; ++d) { c[d] = g_cost[(size_t)d*HW + p]; m = fmaxf(m, c[d]); }
    float S = 0.f;
    #pragma unroll
    for (int d = 0; d < DD; ++d) { c[d] = expf(c[d] - m); S += c[d]; }
    float inv = 1.0f / S;
    float depth = 0.f, fid = 0.f;
    #pragma unroll
    for (int d = 0; d < DD; ++d) {
        float pr = c[d] * inv;
        depth = fmaf(pr, dvals[(size_t)d*HW + p], depth);
        fid   = fmaf(pr, (float)d, fid);
    }
    int di = (int)fid;
    di = max(0, min(DD-1, di));
    float conf = 0.f;
    #pragma unroll
    for (int d = 0; d < DD; ++d)
        if (d >= di-1 && d <= di+2) conf += c[d] * inv;
    out[p]      = depth;
    out[HW + p] = conf;
}

// ---------------------------------------------------------------------------
// Launch
// ---------------------------------------------------------------------------
extern "C" void kernel_launch(void* const* d_in, const int* in_sizes, int n_in,
                              void* d_out, int out_size) {
    const float* features = (const float*)d_in[0];
    const float* proj     = (const float*)d_in[1];
    const float* dvals    = (const float*)d_in[2];
    const float* w0 = (const float*)d_in[3];
    const float* b0 = (const float*)d_in[4];
    const float* w1 = (const float*)d_in[5];
    const float* b1 = (const float*)d_in[6];
    const float* w2 = (const float*)d_in[7];
    const float* b2 = (const float*)d_in[8];
    float* out = (float*)d_out;

    // smem: weights + NSL padded slices of (10*18*PS) floats
    const int smem0 = (27*32*8 + 6*10*18*36) * 4;   // 27648+155520 = 183168 B
    const int smem1 = (27*8*8  + 8*10*18*12) * 4;   //  6912+ 69120 =  76032 B
    const int smem2 = (27*8*1  + 8*10*18*12) * 4;   //   864+ 69120 =  69984 B
    cudaFuncSetAttribute(k_conv<0>, cudaFuncAttributeMaxDynamicSharedMemorySize, smem0);
    cudaFuncSetAttribute(k_conv<1>, cudaFuncAttributeMaxDynamicSharedMemorySize, smem1);
    cudaFuncSetAttribute(k_conv<2>, cudaFuncAttributeMaxDynamicSharedMemorySize, smem2);

    k_xform<<<1, 1>>>(proj);
    k_transpose<<<(VV*HW*CC + 255)/256, 256>>>(features);
    k_warpvar<<<(DHW + 127)/128, 128>>>(dvals);

    dim3 cgrid0(WW/16, HH/8, DD/4);   // (10, 16, 12)
    dim3 cgrid1(WW/16, HH/8, DD/6);   // (10, 16, 8)
    k_conv<0><<<cgrid0, 128, smem0>>>(w0, b0);
    k_conv<1><<<cgrid1, 128, smem1>>>(w1, b1);
    k_conv<2><<<cgrid1, 128, smem2>>>(w2, b2);

    k_softmax<<<(HW + 255)/256, 256>>>(dvals, out);
}

// round 4
// speedup vs baseline: 2.4138x; 1.1240x over previous
#include <cuda_runtime.h>
#include <math.h>

#define VV 3
#define CC 32
#define DD 48
#define HH 128
#define WW 160
#define HW (HH*WW)        /* 20480 */
#define DHW (DD*HW)       /* 983040 */

// ---------------------------------------------------------------------------
// Scratch
// ---------------------------------------------------------------------------
__device__ float g_xform[2][12];
__device__ float g_feat_t[(size_t)VV*HW*CC];     // channels-last features
__device__ float g_var[(size_t)DHW*CC];          // variance volume [D,H,W,32]
__device__ float g_h0[(size_t)DHW*8];            // conv0 out [D,H,W,8]
__device__ float g_h1[(size_t)DHW*8];            // conv1 out [D,H,W,8]
__device__ float g_cost[(size_t)DHW];            // conv2 out [D,H,W]

// packed fp32 helpers (Blackwell f32x2)
__device__ __forceinline__ void fma2(unsigned long long& d,
                                     unsigned long long a,
                                     unsigned long long b) {
    asm("fma.rn.f32x2 %0, %1, %2, %0;" : "+l"(d) : "l"(a), "l"(b));
}
__device__ __forceinline__ float unpack_sum(unsigned long long v) {
    float lo, hi;
    asm("mov.b64 {%0, %1}, %2;" : "=f"(lo), "=f"(hi) : "l"(v));
    return lo + hi;
}

// ---------------------------------------------------------------------------
// Kernel 1: projective transforms  M_v = C_v * inv(C_0)
// ---------------------------------------------------------------------------
__global__ void k_xform(const float* __restrict__ proj) {
    if (threadIdx.x || blockIdx.x) return;
    double Cm[3][4][4];
    for (int v = 0; v < 3; ++v) {
        double K[3][3], E[4][4];
        for (int i = 0; i < 3; ++i)
            for (int j = 0; j < 3; ++j)
                K[i][j] = (double)proj[((v*2+1)*4+i)*4+j];
        for (int i = 0; i < 4; ++i)
            for (int j = 0; j < 4; ++j)
                E[i][j] = (double)proj[((v*2+0)*4+i)*4+j];
        for (int i = 0; i < 3; ++i)
            for (int j = 0; j < 4; ++j) {
                double s = 0.0;
                for (int k = 0; k < 3; ++k) s += K[i][k]*E[k][j];
                Cm[v][i][j] = s;
            }
        for (int j = 0; j < 4; ++j) Cm[v][3][j] = E[3][j];
    }
    double A[4][8];
    for (int i = 0; i < 4; ++i)
        for (int j = 0; j < 4; ++j) { A[i][j] = Cm[0][i][j]; A[i][4+j] = (i==j) ? 1.0 : 0.0; }
    for (int col = 0; col < 4; ++col) {
        int piv = col;
        for (int r = col+1; r < 4; ++r) if (fabs(A[r][col]) > fabs(A[piv][col])) piv = r;
        if (piv != col)
            for (int j = 0; j < 8; ++j) { double t = A[col][j]; A[col][j] = A[piv][j]; A[piv][j] = t; }
        double iv = 1.0 / A[col][col];
        for (int j = 0; j < 8; ++j) A[col][j] *= iv;
        for (int r = 0; r < 4; ++r) if (r != col) {
            double f = A[r][col];
            for (int j = 0; j < 8; ++j) A[r][j] -= f * A[col][j];
        }
    }
    for (int v = 1; v < 3; ++v) {
        double M[3][4];
        for (int i = 0; i < 3; ++i)
            for (int j = 0; j < 4; ++j) {
                double s = 0.0;
                for (int k = 0; k < 4; ++k) s += Cm[v][i][k] * A[k][4+j];
                M[i][j] = s;
            }
        float* o = g_xform[v-1];
        o[0]=(float)M[0][0]; o[1]=(float)M[0][1]; o[2]=(float)M[0][2];
        o[3]=(float)M[1][0]; o[4]=(float)M[1][1]; o[5]=(float)M[1][2];
        o[6]=(float)M[2][0]; o[7]=(float)M[2][1]; o[8]=(float)M[2][2];
        o[9]=(float)M[0][3]; o[10]=(float)M[1][3]; o[11]=(float)M[2][3];
    }
}

// ---------------------------------------------------------------------------
// Kernel 2: transpose features [V,C,H,W] -> [V,H,W,C]
// ---------------------------------------------------------------------------
__global__ void k_transpose(const float* __restrict__ f) {
    int i = blockIdx.x*blockDim.x + threadIdx.x;
    if (i >= VV*HW*CC) return;
    int c  = i & (CC-1);
    int hw = (i >> 5) % HW;
    int v  = i / (HW*CC);
    g_feat_t[i] = f[((size_t)v*CC + c)*HW + hw];
}

// ---------------------------------------------------------------------------
// Kernel 3: fused homography warp + bilinear sample + variance
// ---------------------------------------------------------------------------
__global__ void __launch_bounds__(128) k_warpvar(const float* __restrict__ dvals) {
    int idx = blockIdx.x*blockDim.x + threadIdx.x;
    if (idx >= DHW) return;
    int w = idx % WW;
    int h = (idx / WW) % HH;
    float depth = dvals[idx];

    int   offs[2][4];
    float cwts[2][4];
    #pragma unroll
    for (int v = 0; v < 2; ++v) {
        const float* xf = g_xform[v];
        float x = (float)w, y = (float)h;
        float rx = xf[0]*x + xf[1]*y + xf[2];
        float ry = xf[3]*x + xf[4]*y + xf[5];
        float rz = xf[6]*x + xf[7]*y + xf[8];
        float px = rx*depth + xf[9];
        float py = ry*depth + xf[10];
        float pz = rz*depth + xf[11];
        float gx = px / pz / ((float)(WW-1)*0.5f) - 1.0f;
        float gy = py / pz / ((float)(HH-1)*0.5f) - 1.0f;
        float sx = (gx + 1.0f) * 0.5f * (float)(WW-1);
        float sy = (gy + 1.0f) * 0.5f * (float)(HH-1);
        float x0 = floorf(sx), y0 = floorf(sy);
        float wx1 = sx - x0, wx0 = 1.0f - wx1;
        float wy1 = sy - y0, wy0 = 1.0f - wy1;
        float cx[2] = {x0, x0+1.0f}, cy[2] = {y0, y0+1.0f};
        float wx[2] = {wx0, wx1}, wy[2] = {wy0, wy1};
        #pragma unroll
        for (int cyi = 0; cyi < 2; ++cyi)
        #pragma unroll
        for (int cxi = 0; cxi < 2; ++cxi) {
            float xi = cx[cxi], yi = cy[cyi];
            bool valid = (xi >= 0.0f) && (xi <= (float)(WW-1)) &&
                         (yi >= 0.0f) && (yi <= (float)(HH-1));
            float xc = fminf(fmaxf(xi, 0.0f), (float)(WW-1));
            float yc = fminf(fmaxf(yi, 0.0f), (float)(HH-1));
            int ii = (int)yc * WW + (int)xc;
            offs[v][cyi*2+cxi] = ii * CC;
            cwts[v][cyi*2+cxi] = wx[cxi]*wy[cyi] * (valid ? 1.0f : 0.0f);
        }
    }

    const float4* refp = (const float4*)(g_feat_t + (size_t)(h*WW + w)*CC);
    const float* s1 = g_feat_t + (size_t)HW*CC;
    const float* s2 = g_feat_t + (size_t)2*HW*CC;
    float4* outp = (float4*)(g_var + (size_t)idx*CC);

    #pragma unroll
    for (int g = 0; g < 8; ++g) {
        float4 r = refp[g];
        float sx_ = r.x, sy_ = r.y, sz_ = r.z, sw_ = r.w;
        float qx = r.x*r.x, qy = r.y*r.y, qz = r.z*r.z, qw = r.w*r.w;
        #pragma unroll
        for (int v = 0; v < 2; ++v) {
            const float* base = (v == 0) ? s1 : s2;
            float wxp = 0.f, wyp = 0.f, wzp = 0.f, wwp = 0.f;
            #pragma unroll
            for (int k = 0; k < 4; ++k) {
                float cw = cwts[v][k];
                const float4 f = *((const float4*)(base + offs[v][k]) + g);
                wxp = fmaf(cw, f.x, wxp);
                wyp = fmaf(cw, f.y, wyp);
                wzp = fmaf(cw, f.z, wzp);
                wwp = fmaf(cw, f.w, wwp);
            }
            sx_ += wxp; sy_ += wyp; sz_ += wzp; sw_ += wwp;
            qx = fmaf(wxp, wxp, qx); qy = fmaf(wyp, wyp, qy);
            qz = fmaf(wzp, wzp, qz); qw = fmaf(wwp, wwp, qw);
        }
        float4 o;
        float mx = sx_ / 3.0f, my = sy_ / 3.0f, mz = sz_ / 3.0f, mw = sw_ / 3.0f;
        o.x = qx / 3.0f - mx*mx;
        o.y = qy / 3.0f - my*my;
        o.z = qz / 3.0f - mz*mz;
        o.w = qw / 3.0f - mw*mw;
        outp[g] = o;
    }
}

// ---------------------------------------------------------------------------
// Kernel 4: conv0 (32->8), 256 threads, 16x16 tile, DS=2.
// Channel-rotation swizzle: group g of pixel p lives at p*32 + ((p+g)&7)*4.
// Conflict-free LDS.128 with zero padding -> slab fits with 8 warps/SM.
// ---------------------------------------------------------------------------
__global__ void __launch_bounds__(256, 1)
k_conv0(const float* __restrict__ wgt, const float* __restrict__ bias) {
    constexpr int CIN = 32, COUT = 8, G = 8;
    constexpr int TH = 16, TW = 16, DS = 2, NSL = 4;
    constexpr int SLICE = (TH+2)*(TW+2)*CIN;     // 18*18*32 = 10368 floats

    extern __shared__ float sm[];
    float* s_w  = sm;                            // 27*32*8 = 6912 floats
    float* slab = sm + 27*CIN*COUT;

    const int tid = threadIdx.x;
    const int tx = tid % TW, ty = tid / TW;
    const int w0 = blockIdx.x * TW;
    const int h0 = blockIdx.y * TH;
    const int d0 = blockIdx.z * DS;

    for (int i = tid; i < 27*CIN*COUT; i += 256) {
        int j   = i & 3;
        int co  = (i >> 2) % COUT;
        int rem = i / (4*COUT);
        int g   = rem % G;
        int tap = rem / G;
        s_w[i] = wgt[(co*CIN + g*4 + j)*27 + tap];
    }

    // load NSL slices with rotation swizzle
    {
        const int NTOT = NSL * (TH+2)*(TW+2) * G;    // float4 units
        for (int i = tid; i < NTOT; i += 256) {
            int g   = i % G;
            int col = (i / G) % (TW+2);
            int rem = i / (G*(TW+2));
            int row = rem % (TH+2);
            int s   = rem / (TH+2);
            int z  = d0 - 1 + s;
            int gh = h0 - 1 + row;
            int gw = w0 - 1 + col;
            float4 v = make_float4(0.f, 0.f, 0.f, 0.f);
            if (z >= 0 && z < DD && gh >= 0 && gh < HH && gw >= 0 && gw < WW)
                v = *(const float4*)(g_var + (((size_t)z*HH + gh)*WW + gw)*CIN + g*4);
            int pix = row*(TW+2) + col;
            *(float4*)(slab + s*SLICE + pix*CIN + (((pix + g) & 7) << 2)) = v;
        }
    }
    __syncthreads();

    unsigned long long acc[DS][COUT];
    #pragma unroll
    for (int o = 0; o < DS; ++o)
        #pragma unroll
        for (int co = 0; co < COUT; ++co) acc[o][co] = 0ull;

    #pragma unroll 1
    for (int kh = 0; kh < 3; ++kh) {
        #pragma unroll 1
        for (int kw = 0; kw < 3; ++kw) {
            const int pix = (ty+kh)*(TW+2) + (tx+kw);
            const float* xb = slab + pix*CIN;
            const int rot = pix & 7;
            const float* wb = s_w + (kh*3 + kw)*G*COUT*4;
            #pragma unroll 2
            for (int g = 0; g < G; ++g) {
                const int go = (((g + rot) & 7) << 2);
                ulonglong2 xv[NSL];
                #pragma unroll
                for (int s = 0; s < NSL; ++s)
                    xv[s] = *(const ulonglong2*)(xb + s*SLICE + go);
                #pragma unroll
                for (int kd = 0; kd < 3; ++kd) {
                    const ulonglong2* wp =
                        (const ulonglong2*)(wb + kd*9*G*COUT*4 + g*COUT*4);
                    ulonglong2 wv[COUT];
                    #pragma unroll
                    for (int co = 0; co < COUT; ++co) wv[co] = wp[co];
                    #pragma unroll
                    for (int o = 0; o < DS; ++o) {
                        #pragma unroll
                        for (int co = 0; co < COUT; ++co) {
                            fma2(acc[o][co], xv[o+kd].x, wv[co].x);
                            fma2(acc[o][co], xv[o+kd].y, wv[co].y);
                        }
                    }
                }
            }
        }
    }

    float bb[COUT];
    #pragma unroll
    for (int co = 0; co < COUT; ++co) bb[co] = bias[co];

    #pragma unroll
    for (int o = 0; o < DS; ++o) {
        int d = d0 + o;
        float* op = g_h0 + (((size_t)d*HH + (h0+ty))*WW + (w0+tx))*COUT;
        float r[8];
        #pragma unroll
        for (int co = 0; co < 8; ++co) {
            float v = unpack_sum(acc[o][co]) + bb[co];
            r[co] = fmaxf(v, 0.f);
        }
        ((float4*)op)[0] = make_float4(r[0], r[1], r[2], r[3]);
        ((float4*)op)[1] = make_float4(r[4], r[5], r[6], r[7]);
    }
}

// ---------------------------------------------------------------------------
// Kernels 5-6: conv1 (8->8) / conv2 (8->1). 128 threads, DS=4, padded PS=12,
// 3 blocks/SM for latency hiding.
// ---------------------------------------------------------------------------
template<int STAGE>
__global__ void __launch_bounds__(128, 3)
k_conv(const float* __restrict__ wgt, const float* __restrict__ bias) {
    constexpr int CIN   = 8;
    constexpr int COUT  = (STAGE == 2) ? 1 : 8;
    constexpr bool RELU = (STAGE != 2);
    constexpr int TH = 8, TW = 16, DS = 4, NSL = 6;
    constexpr int G = CIN / 4;
    constexpr int PS = CIN + 4;
    constexpr int SLICE = (TH+2)*(TW+2)*PS;

    const float* __restrict__ x   = (STAGE == 1) ? g_h0 : g_h1;
    float*       __restrict__ out = (STAGE == 1) ? g_h1 : g_cost;

    extern __shared__ float sm[];
    float* s_w  = sm;
    float* slab = sm + 27*CIN*COUT;

    const int tid = threadIdx.x;
    const int tx = tid % TW, ty = tid / TW;
    const int w0 = blockIdx.x * TW;
    const int h0 = blockIdx.y * TH;
    const int d0 = blockIdx.z * DS;

    for (int i = tid; i < 27*CIN*COUT; i += 128) {
        int j   = i & 3;
        int co  = (i >> 2) % COUT;
        int rem = i / (4*COUT);
        int g   = rem % G;
        int tap = rem / G;
        s_w[i] = wgt[(co*CIN + g*4 + j)*27 + tap];
    }

    {
        const int NTOT = NSL * (TH+2)*(TW+2) * G;
        for (int i = tid; i < NTOT; i += 128) {
            int g   = i % G;
            int col = (i / G) % (TW+2);
            int rem = i / (G*(TW+2));
            int row = rem % (TH+2);
            int s   = rem / (TH+2);
            int z  = d0 - 1 + s;
            int gh = h0 - 1 + row;
            int gw = w0 - 1 + col;
            float4 v = make_float4(0.f, 0.f, 0.f, 0.f);
            if (z >= 0 && z < DD && gh >= 0 && gh < HH && gw >= 0 && gw < WW)
                v = *(const float4*)(x + (((size_t)z*HH + gh)*WW + gw)*CIN + g*4);
            *(float4*)(slab + ((s*(TH+2) + row)*(TW+2) + col)*PS + g*4) = v;
        }
    }
    __syncthreads();

    unsigned long long acc[DS][COUT];
    #pragma unroll
    for (int o = 0; o < DS; ++o)
        #pragma unroll
        for (int co = 0; co < COUT; ++co) acc[o][co] = 0ull;

    #pragma unroll 1
    for (int kh = 0; kh < 3; ++kh) {
        #pragma unroll 1
        for (int kw = 0; kw < 3; ++kw) {
            const float* xb = slab + ((ty+kh)*(TW+2) + (tx+kw))*PS;
            const float* wb = s_w + (kh*3 + kw)*G*COUT*4;
            #pragma unroll
            for (int g = 0; g < G; ++g) {
                ulonglong2 xv[NSL];
                #pragma unroll
                for (int s = 0; s < NSL; ++s)
                    xv[s] = *(const ulonglong2*)(xb + s*SLICE + g*4);
                #pragma unroll
                for (int kd = 0; kd < 3; ++kd) {
                    const ulonglong2* wp =
                        (const ulonglong2*)(wb + kd*9*G*COUT*4 + g*COUT*4);
                    ulonglong2 wv[COUT];
                    #pragma unroll
                    for (int co = 0; co < COUT; ++co) wv[co] = wp[co];
                    #pragma unroll
                    for (int o = 0; o < DS; ++o) {
                        #pragma unroll
                        for (int co = 0; co < COUT; ++co) {
                            fma2(acc[o][co], xv[o+kd].x, wv[co].x);
                            fma2(acc[o][co], xv[o+kd].y, wv[co].y);
                        }
                    }
                }
            }
        }
    }

    float bb[COUT];
    #pragma unroll
    for (int co = 0; co < COUT; ++co) bb[co] = bias[co];

    #pragma unroll
    for (int o = 0; o < DS; ++o) {
        int d = d0 + o;
        float* op = out + (((size_t)d*HH + (h0+ty))*WW + (w0+tx))*COUT;
        if constexpr (COUT == 8) {
            float r[8];
            #pragma unroll
            for (int co = 0; co < 8; ++co) {
                float v = unpack_sum(acc[o][co]) + bb[co];
                r[co] = RELU ? fmaxf(v, 0.f) : v;
            }
            ((float4*)op)[0] = make_float4(r[0], r[1], r[2], r[3]);
            ((float4*)op)[1] = make_float4(r[4], r[5], r[6], r[7]);
        } else {
            float v = unpack_sum(acc[o][0]) + bb[0];
            op[0] = RELU ? fmaxf(v, 0.f) : v;
        }
    }
}

// ---------------------------------------------------------------------------
// Kernel 7: softmax over D + expected depth + 4-tap confidence
// ---------------------------------------------------------------------------
__global__ void k_softmax(const float* __restrict__ dvals, float* __restrict__ out) {
    int p = blockIdx.x*blockDim.x + threadIdx.x;
    if (p >= HW) return;
    float c[DD];
    float m = -1e30f;
    #pragma unroll
    for (int d = 0; d < DD; ++d) { c[d] = g_cost[(size_t)d*HW + p]; m = fmaxf(m, c[d]); }
    float S = 0.f;
    #pragma unroll
    for (int d = 0; d < DD; ++d) { c[d] = expf(c[d] - m); S += c[d]; }
    float inv = 1.0f / S;
    float depth = 0.f, fid = 0.f;
    #pragma unroll
    for (int d = 0; d < DD; ++d) {
        float pr = c[d] * inv;
        depth = fmaf(pr, dvals[(size_t)d*HW + p], depth);
        fid   = fmaf(pr, (float)d, fid);
    }
    int di = (int)fid;
    di = max(0, min(DD-1, di));
    float conf = 0.f;
    #pragma unroll
    for (int d = 0; d < DD; ++d)
        if (d >= di-1 && d <= di+2) conf += c[d] * inv;
    out[p]      = depth;
    out[HW + p] = conf;
}

// ---------------------------------------------------------------------------
// Launch
// ---------------------------------------------------------------------------
extern "C" void kernel_launch(void* const* d_in, const int* in_sizes, int n_in,
                              void* d_out, int out_size) {
    const float* features = (const float*)d_in[0];
    const float* proj     = (const float*)d_in[1];
    const float* dvals    = (const float*)d_in[2];
    const float* w0 = (const float*)d_in[3];
    const float* b0 = (const float*)d_in[4];
    const float* w1 = (const float*)d_in[5];
    const float* b1 = (const float*)d_in[6];
    const float* w2 = (const float*)d_in[7];
    const float* b2 = (const float*)d_in[8];
    float* out = (float*)d_out;

    const int smem0 = (27*32*8 + 4*18*18*32) * 4;   // 27648+165888 = 193536 B
    const int smem1 = (27*8*8  + 6*10*18*12) * 4;   //  6912+ 51840 =  58752 B
    const int smem2 = (27*8*1  + 6*10*18*12) * 4;   //   864+ 51840 =  52704 B
    cudaFuncSetAttribute(k_conv0,    cudaFuncAttributeMaxDynamicSharedMemorySize, smem0);
    cudaFuncSetAttribute(k_conv<1>,  cudaFuncAttributeMaxDynamicSharedMemorySize, smem1);
    cudaFuncSetAttribute(k_conv<2>,  cudaFuncAttributeMaxDynamicSharedMemorySize, smem2);

    k_xform<<<1, 1>>>(proj);
    k_transpose<<<(VV*HW*CC + 255)/256, 256>>>(features);
    k_warpvar<<<(DHW + 127)/128, 128>>>(dvals);

    dim3 cgrid0(WW/16, HH/16, DD/2);   // (10, 8, 24)
    dim3 cgrid12(WW/16, HH/8, DD/4);   // (10, 16, 12)
    k_conv0<<<cgrid0, 256, smem0>>>(w0, b0);
    k_conv<1><<<cgrid12, 128, smem1>>>(w1, b1);
    k_conv<2><<<cgrid12, 128, smem2>>>(w2, b2);

    k_softmax<<<(HW + 255)/256, 256>>>(dvals, out);
}

// round 5
// speedup vs baseline: 3.1567x; 1.3078x over previous
#include <cuda_runtime.h>
#include <math.h>

#define VV 3
#define CC 32
#define DD 48
#define HH 128
#define WW 160
#define HW (HH*WW)        /* 20480 */
#define DHW (DD*HW)       /* 983040 */

// ---------------------------------------------------------------------------
// Scratch
// ---------------------------------------------------------------------------
__device__ float g_xform[2][12];
__device__ float g_feat_t[(size_t)VV*HW*CC];     // channels-last features
__device__ float g_var[(size_t)DHW*CC];          // variance volume [D,H,W,32]
__device__ float g_h0[(size_t)DHW*8];            // conv0 out [D,H,W,8]
__device__ float g_h1[(size_t)DHW*8];            // conv1 out [D,H,W,8]
__device__ float g_cost[(size_t)DHW];            // conv2 out [D,H,W]

// packed fp32 helpers (Blackwell f32x2)
__device__ __forceinline__ void fma2(unsigned long long& d,
                                     unsigned long long a,
                                     unsigned long long b) {
    asm("fma.rn.f32x2 %0, %1, %2, %0;" : "+l"(d) : "l"(a), "l"(b));
}
__device__ __forceinline__ float unpack_sum(unsigned long long v) {
    float lo, hi;
    asm("mov.b64 {%0, %1}, %2;" : "=f"(lo), "=f"(hi) : "l"(v));
    return lo + hi;
}

// ---------------------------------------------------------------------------
// Kernel 1: projective transforms  M_v = C_v * inv(C_0)
// ---------------------------------------------------------------------------
__global__ void k_xform(const float* __restrict__ proj) {
    if (threadIdx.x || blockIdx.x) return;
    double Cm[3][4][4];
    for (int v = 0; v < 3; ++v) {
        double K[3][3], E[4][4];
        for (int i = 0; i < 3; ++i)
            for (int j = 0; j < 3; ++j)
                K[i][j] = (double)proj[((v*2+1)*4+i)*4+j];
        for (int i = 0; i < 4; ++i)
            for (int j = 0; j < 4; ++j)
                E[i][j] = (double)proj[((v*2+0)*4+i)*4+j];
        for (int i = 0; i < 3; ++i)
            for (int j = 0; j < 4; ++j) {
                double s = 0.0;
                for (int k = 0; k < 3; ++k) s += K[i][k]*E[k][j];
                Cm[v][i][j] = s;
            }
        for (int j = 0; j < 4; ++j) Cm[v][3][j] = E[3][j];
    }
    double A[4][8];
    for (int i = 0; i < 4; ++i)
        for (int j = 0; j < 4; ++j) { A[i][j] = Cm[0][i][j]; A[i][4+j] = (i==j) ? 1.0 : 0.0; }
    for (int col = 0; col < 4; ++col) {
        int piv = col;
        for (int r = col+1; r < 4; ++r) if (fabs(A[r][col]) > fabs(A[piv][col])) piv = r;
        if (piv != col)
            for (int j = 0; j < 8; ++j) { double t = A[col][j]; A[col][j] = A[piv][j]; A[piv][j] = t; }
        double iv = 1.0 / A[col][col];
        for (int j = 0; j < 8; ++j) A[col][j] *= iv;
        for (int r = 0; r < 4; ++r) if (r != col) {
            double f = A[r][col];
            for (int j = 0; j < 8; ++j) A[r][j] -= f * A[col][j];
        }
    }
    for (int v = 1; v < 3; ++v) {
        double M[3][4];
        for (int i = 0; i < 3; ++i)
            for (int j = 0; j < 4; ++j) {
                double s = 0.0;
                for (int k = 0; k < 4; ++k) s += Cm[v][i][k] * A[k][4+j];
                M[i][j] = s;
            }
        float* o = g_xform[v-1];
        o[0]=(float)M[0][0]; o[1]=(float)M[0][1]; o[2]=(float)M[0][2];
        o[3]=(float)M[1][0]; o[4]=(float)M[1][1]; o[5]=(float)M[1][2];
        o[6]=(float)M[2][0]; o[7]=(float)M[2][1]; o[8]=(float)M[2][2];
        o[9]=(float)M[0][3]; o[10]=(float)M[1][3]; o[11]=(float)M[2][3];
    }
}

// ---------------------------------------------------------------------------
// Kernel 2: tiled transpose [V,C,H,W] -> [V,H,W,C], coalesced both sides
// ---------------------------------------------------------------------------
__global__ void k_transpose(const float* __restrict__ f) {
    __shared__ float t[32][33];
    int v   = blockIdx.y;
    int hw0 = blockIdx.x * 32;
    for (int i = threadIdx.y; i < 32; i += 8)
        t[i][threadIdx.x] = f[((size_t)v*32 + i)*HW + hw0 + threadIdx.x];
    __syncthreads();
    for (int i = threadIdx.y; i < 32; i += 8)
        g_feat_t[((size_t)v*HW + hw0 + i)*32 + threadIdx.x] = t[threadIdx.x][i];
}

// ---------------------------------------------------------------------------
// Kernel 3: warp+variance, lane-per-channel-group layout.
// 8 consecutive lanes handle the 8 float4 channel-groups of ONE voxel, so each
// gather instruction touches only 4 cache lines (vs 32 before).
// ---------------------------------------------------------------------------
__global__ void __launch_bounds__(256) k_warpvar(const float* __restrict__ dvals) {
    long long t = (long long)blockIdx.x*256 + threadIdx.x;
    int g   = (int)(t & 7);
    int idx = (int)(t >> 3);
    if (idx >= DHW) return;
    int w = idx % WW;
    int h = (idx / WW) % HH;
    float depth = dvals[idx];

    int   offs[2][4];
    float cwts[2][4];
    #pragma unroll
    for (int v = 0; v < 2; ++v) {
        const float* xf = g_xform[v];
        float x = (float)w, y = (float)h;
        float rx = xf[0]*x + xf[1]*y + xf[2];
        float ry = xf[3]*x + xf[4]*y + xf[5];
        float rz = xf[6]*x + xf[7]*y + xf[8];
        float px = rx*depth + xf[9];
        float py = ry*depth + xf[10];
        float pz = rz*depth + xf[11];
        float gx = px / pz / ((float)(WW-1)*0.5f) - 1.0f;
        float gy = py / pz / ((float)(HH-1)*0.5f) - 1.0f;
        float sx = (gx + 1.0f) * 0.5f * (float)(WW-1);
        float sy = (gy + 1.0f) * 0.5f * (float)(HH-1);
        float x0 = floorf(sx), y0 = floorf(sy);
        float wx1 = sx - x0, wx0 = 1.0f - wx1;
        float wy1 = sy - y0, wy0 = 1.0f - wy1;
        float cx[2] = {x0, x0+1.0f}, cy[2] = {y0, y0+1.0f};
        float wx[2] = {wx0, wx1}, wy[2] = {wy0, wy1};
        #pragma unroll
        for (int cyi = 0; cyi < 2; ++cyi)
        #pragma unroll
        for (int cxi = 0; cxi < 2; ++cxi) {
            float xi = cx[cxi], yi = cy[cyi];
            bool valid = (xi >= 0.0f) && (xi <= (float)(WW-1)) &&
                         (yi >= 0.0f) && (yi <= (float)(HH-1));
            float xc = fminf(fmaxf(xi, 0.0f), (float)(WW-1));
            float yc = fminf(fmaxf(yi, 0.0f), (float)(HH-1));
            int ii = (int)yc * WW + (int)xc;
            offs[v][cyi*2+cxi] = ii * CC + g*4;
            cwts[v][cyi*2+cxi] = wx[cxi]*wy[cyi] * (valid ? 1.0f : 0.0f);
        }
    }

    float4 r = *(const float4*)(g_feat_t + (size_t)(h*WW + w)*CC + g*4);
    const float* s1 = g_feat_t + (size_t)HW*CC;
    const float* s2 = g_feat_t + (size_t)2*HW*CC;

    float sx_ = r.x, sy_ = r.y, sz_ = r.z, sw_ = r.w;
    float qx = r.x*r.x, qy = r.y*r.y, qz = r.z*r.z, qw = r.w*r.w;
    #pragma unroll
    for (int v = 0; v < 2; ++v) {
        const float* base = (v == 0) ? s1 : s2;
        float wxp = 0.f, wyp = 0.f, wzp = 0.f, wwp = 0.f;
        #pragma unroll
        for (int k = 0; k < 4; ++k) {
            float cw = cwts[v][k];
            const float4 f = *(const float4*)(base + offs[v][k]);
            wxp = fmaf(cw, f.x, wxp);
            wyp = fmaf(cw, f.y, wyp);
            wzp = fmaf(cw, f.z, wzp);
            wwp = fmaf(cw, f.w, wwp);
        }
        sx_ += wxp; sy_ += wyp; sz_ += wzp; sw_ += wwp;
        qx = fmaf(wxp, wxp, qx); qy = fmaf(wyp, wyp, qy);
        qz = fmaf(wzp, wzp, qz); qw = fmaf(wwp, wwp, qw);
    }
    float4 o;
    float mx = sx_ / 3.0f, my = sy_ / 3.0f, mz = sz_ / 3.0f, mw = sw_ / 3.0f;
    o.x = qx / 3.0f - mx*mx;
    o.y = qy / 3.0f - my*my;
    o.z = qz / 3.0f - mz*mz;
    o.w = qw / 3.0f - mw*mw;
    *(float4*)(g_var + (size_t)idx*CC + g*4) = o;
}

// ---------------------------------------------------------------------------
// Kernel 4: conv0 (32->8). 256 threads = 2 d-layers x (8x16 tile).
// Shared 8-slice slab; each thread DS=3 depth outputs. Rotation swizzle.
// ---------------------------------------------------------------------------
__global__ void __launch_bounds__(256, 1)
k_conv0(const float* __restrict__ wgt, const float* __restrict__ bias) {
    constexpr int CIN = 32, COUT = 8, G = 8;
    constexpr int TH = 8, TW = 16, DS = 3, NSL = 8;
    constexpr int SLICE = (TH+2)*(TW+2)*CIN;     // 10*18*32 = 5760 floats

    extern __shared__ float sm[];
    float* s_w  = sm;                            // 6912 floats
    float* slab = sm + 27*CIN*COUT;

    const int tid = threadIdx.x;
    const int zl  = tid >> 7;                    // d-layer 0/1
    const int t   = tid & 127;
    const int tx = t % TW, ty = t / TW;
    const int w0 = blockIdx.x * TW;
    const int h0 = blockIdx.y * TH;
    const int d0 = blockIdx.z * (2*DS);

    for (int i = tid; i < 27*CIN*COUT; i += 256) {
        int j   = i & 3;
        int co  = (i >> 2) % COUT;
        int rem = i / (4*COUT);
        int g   = rem % G;
        int tap = rem / G;
        s_w[i] = wgt[(co*CIN + g*4 + j)*27 + tap];
    }

    {
        const int NTOT = NSL * (TH+2)*(TW+2) * G;    // float4 units
        for (int i = tid; i < NTOT; i += 256) {
            int g   = i % G;
            int col = (i / G) % (TW+2);
            int rem = i / (G*(TW+2));
            int row = rem % (TH+2);
            int s   = rem / (TH+2);
            int z  = d0 - 1 + s;
            int gh = h0 - 1 + row;
            int gw = w0 - 1 + col;
            float4 v = make_float4(0.f, 0.f, 0.f, 0.f);
            if (z >= 0 && z < DD && gh >= 0 && gh < HH && gw >= 0 && gw < WW)
                v = *(const float4*)(g_var + (((size_t)z*HH + gh)*WW + gw)*CIN + g*4);
            int pix = row*(TW+2) + col;
            *(float4*)(slab + s*SLICE + pix*CIN + (((pix + g) & 7) << 2)) = v;
        }
    }
    __syncthreads();

    unsigned long long acc[DS][COUT];
    #pragma unroll
    for (int o = 0; o < DS; ++o)
        #pragma unroll
        for (int co = 0; co < COUT; ++co) acc[o][co] = 0ull;

    const int zb = zl * DS;                      // first slice this layer reads

    #pragma unroll 1
    for (int kh = 0; kh < 3; ++kh) {
        #pragma unroll 1
        for (int kw = 0; kw < 3; ++kw) {
            const int pix = (ty+kh)*(TW+2) + (tx+kw);
            const float* xb = slab + pix*CIN;
            const int rot = pix & 7;
            const float* wb = s_w + (kh*3 + kw)*G*COUT*4;
            #pragma unroll 2
            for (int g = 0; g < G; ++g) {
                const int go = (((g + rot) & 7) << 2);
                ulonglong2 xv[DS+2];
                #pragma unroll
                for (int s = 0; s < DS+2; ++s)
                    xv[s] = *(const ulonglong2*)(xb + (zb+s)*SLICE + go);
                #pragma unroll
                for (int kd = 0; kd < 3; ++kd) {
                    const ulonglong2* wp =
                        (const ulonglong2*)(wb + kd*9*G*COUT*4 + g*COUT*4);
                    ulonglong2 wv[COUT];
                    #pragma unroll
                    for (int co = 0; co < COUT; ++co) wv[co] = wp[co];
                    #pragma unroll
                    for (int o = 0; o < DS; ++o) {
                        #pragma unroll
                        for (int co = 0; co < COUT; ++co) {
                            fma2(acc[o][co], xv[o+kd].x, wv[co].x);
                            fma2(acc[o][co], xv[o+kd].y, wv[co].y);
                        }
                    }
                }
            }
        }
    }

    float bb[COUT];
    #pragma unroll
    for (int co = 0; co < COUT; ++co) bb[co] = bias[co];

    #pragma unroll
    for (int o = 0; o < DS; ++o) {
        int d = d0 + zl*DS + o;
        float* op = g_h0 + (((size_t)d*HH + (h0+ty))*WW + (w0+tx))*COUT;
        float r[8];
        #pragma unroll
        for (int co = 0; co < 8; ++co) {
            float v = unpack_sum(acc[o][co]) + bb[co];
            r[co] = fmaxf(v, 0.f);
        }
        ((float4*)op)[0] = make_float4(r[0], r[1], r[2], r[3]);
        ((float4*)op)[1] = make_float4(r[4], r[5], r[6], r[7]);
    }
}

// ---------------------------------------------------------------------------
// Kernels 5-6: conv1 (8->8) / conv2 (8->1). 128 threads, DS=6, padded PS=12,
// 2 blocks/SM.
// ---------------------------------------------------------------------------
template<int STAGE>
__global__ void __launch_bounds__(128, 2)
k_conv(const float* __restrict__ wgt, const float* __restrict__ bias) {
    constexpr int CIN   = 8;
    constexpr int COUT  = (STAGE == 2) ? 1 : 8;
    constexpr bool RELU = (STAGE != 2);
    constexpr int TH = 8, TW = 16, DS = 6, NSL = 8;
    constexpr int G = CIN / 4;
    constexpr int PS = CIN + 4;
    constexpr int SLICE = (TH+2)*(TW+2)*PS;

    const float* __restrict__ x   = (STAGE == 1) ? g_h0 : g_h1;
    float*       __restrict__ out = (STAGE == 1) ? g_h1 : g_cost;

    extern __shared__ float sm[];
    float* s_w  = sm;
    float* slab = sm + 27*CIN*COUT;

    const int tid = threadIdx.x;
    const int tx = tid % TW, ty = tid / TW;
    const int w0 = blockIdx.x * TW;
    const int h0 = blockIdx.y * TH;
    const int d0 = blockIdx.z * DS;

    for (int i = tid; i < 27*CIN*COUT; i += 128) {
        int j   = i & 3;
        int co  = (i >> 2) % COUT;
        int rem = i / (4*COUT);
        int g   = rem % G;
        int tap = rem / G;
        s_w[i] = wgt[(co*CIN + g*4 + j)*27 + tap];
    }

    {
        const int NTOT = NSL * (TH+2)*(TW+2) * G;
        for (int i = tid; i < NTOT; i += 128) {
            int g   = i % G;
            int col = (i / G) % (TW+2);
            int rem = i / (G*(TW+2));
            int row = rem % (TH+2);
            int s   = rem / (TH+2);
            int z  = d0 - 1 + s;
            int gh = h0 - 1 + row;
            int gw = w0 - 1 + col;
            float4 v = make_float4(0.f, 0.f, 0.f, 0.f);
            if (z >= 0 && z < DD && gh >= 0 && gh < HH && gw >= 0 && gw < WW)
                v = *(const float4*)(x + (((size_t)z*HH + gh)*WW + gw)*CIN + g*4);
            *(float4*)(slab + ((s*(TH+2) + row)*(TW+2) + col)*PS + g*4) = v;
        }
    }
    __syncthreads();

    unsigned long long acc[DS][COUT];
    #pragma unroll
    for (int o = 0; o < DS; ++o)
        #pragma unroll
        for (int co = 0; co < COUT; ++co) acc[o][co] = 0ull;

    #pragma unroll 1
    for (int kh = 0; kh < 3; ++kh) {
        #pragma unroll 1
        for (int kw = 0; kw < 3; ++kw) {
            const float* xb = slab + ((ty+kh)*(TW+2) + (tx+kw))*PS;
            const float* wb = s_w + (kh*3 + kw)*G*COUT*4;
            #pragma unroll
            for (int g = 0; g < G; ++g) {
                ulonglong2 xv[NSL];
                #pragma unroll
                for (int s = 0; s < NSL; ++s)
                    xv[s] = *(const ulonglong2*)(xb + s*SLICE + g*4);
                #pragma unroll
                for (int kd = 0; kd < 3; ++kd) {
                    const ulonglong2* wp =
                        (const ulonglong2*)(wb + kd*9*G*COUT*4 + g*COUT*4);
                    ulonglong2 wv[COUT];
                    #pragma unroll
                    for (int co = 0; co < COUT; ++co) wv[co] = wp[co];
                    #pragma unroll
                    for (int o = 0; o < DS; ++o) {
                        #pragma unroll
                        for (int co = 0; co < COUT; ++co) {
                            fma2(acc[o][co], xv[o+kd].x, wv[co].x);
                            fma2(acc[o][co], xv[o+kd].y, wv[co].y);
                        }
                    }
                }
            }
        }
    }

    float bb[COUT];
    #pragma unroll
    for (int co = 0; co < COUT; ++co) bb[co] = bias[co];

    #pragma unroll
    for (int o = 0; o < DS; ++o) {
        int d = d0 + o;
        float* op = out + (((size_t)d*HH + (h0+ty))*WW + (w0+tx))*COUT;
        if constexpr (COUT == 8) {
            float r[8];
            #pragma unroll
            for (int co = 0; co < 8; ++co) {
                float v = unpack_sum(acc[o][co]) + bb[co];
                r[co] = RELU ? fmaxf(v, 0.f) : v;
            }
            ((float4*)op)[0] = make_float4(r[0], r[1], r[2], r[3]);
            ((float4*)op)[1] = make_float4(r[4], r[5], r[6], r[7]);
        } else {
            float v = unpack_sum(acc[o][0]) + bb[0];
            op[0] = RELU ? fmaxf(v, 0.f) : v;
        }
    }
}

// ---------------------------------------------------------------------------
// Kernel 7: softmax over D + expected depth + 4-tap confidence
// ---------------------------------------------------------------------------
__global__ void k_softmax(const float* __restrict__ dvals, float* __restrict__ out) {
    int p = blockIdx.x*blockDim.x + threadIdx.x;
    if (p >= HW) return;
    float c[DD];
    float m = -1e30f;
    #pragma unroll
    for (int d = 0; d < DD; ++d) { c[d] = g_cost[(size_t)d*HW + p]; m = fmaxf(m, c[d]); }
    float S = 0.f;
    #pragma unroll
    for (int d = 0; d < DD; ++d) { c[d] = expf(c[d] - m); S += c[d]; }
    float inv = 1.0f / S;
    float depth = 0.f, fid = 0.f;
    #pragma unroll
    for (int d = 0; d < DD; ++d) {
        float pr = c[d] * inv;
        depth = fmaf(pr, dvals[(size_t)d*HW + p], depth);
        fid   = fmaf(pr, (float)d, fid);
    }
    int di = (int)fid;
    di = max(0, min(DD-1, di));
    float conf = 0.f;
    #pragma unroll
    for (int d = 0; d < DD; ++d)
        if (d >= di-1 && d <= di+2) conf += c[d] * inv;
    out[p]      = depth;
    out[HW + p] = conf;
}

// ---------------------------------------------------------------------------
// Launch
// ---------------------------------------------------------------------------
extern "C" void kernel_launch(void* const* d_in, const int* in_sizes, int n_in,
                              void* d_out, int out_size) {
    const float* features = (const float*)d_in[0];
    const float* proj     = (const float*)d_in[1];
    const float* dvals    = (const float*)d_in[2];
    const float* w0 = (const float*)d_in[3];
    const float* b0 = (const float*)d_in[4];
    const float* w1 = (const float*)d_in[5];
    const float* b1 = (const float*)d_in[6];
    const float* w2 = (const float*)d_in[7];
    const float* b2 = (const float*)d_in[8];
    float* out = (float*)d_out;

    const int smem0 = (27*32*8 + 8*10*18*32) * 4;   // 27648+184320 = 211968 B
    const int smem1 = (27*8*8  + 8*10*18*12) * 4;   //  6912+ 69120 =  76032 B
    const int smem2 = (27*8*1  + 8*10*18*12) * 4;   //   864+ 69120 =  69984 B
    cudaFuncSetAttribute(k_conv0,    cudaFuncAttributeMaxDynamicSharedMemorySize, smem0);
    cudaFuncSetAttribute(k_conv<1>,  cudaFuncAttributeMaxDynamicSharedMemorySize, smem1);
    cudaFuncSetAttribute(k_conv<2>,  cudaFuncAttributeMaxDynamicSharedMemorySize, smem2);

    k_xform<<<1, 1>>>(proj);
    dim3 tgrid(HW/32, VV);
    k_transpose<<<tgrid, dim3(32, 8)>>>(features);
    k_warpvar<<<(DHW*8)/256, 256>>>(dvals);

    dim3 cgrid0(WW/16, HH/8, DD/6);    // (10, 16, 8)
    dim3 cgrid12(WW/16, HH/8, DD/6);   // (10, 16, 8)
    k_conv0<<<cgrid0, 256, smem0>>>(w0, b0);
    k_conv<1><<<cgrid12, 128, smem1>>>(w1, b1);
    k_conv<2><<<cgrid12, 128, smem2>>>(w2, b2);

    k_softmax<<<(HW + 255)/256, 256>>>(dvals, out);
}

// round 6
// speedup vs baseline: 5.0388x; 1.5962x over previous
#include <cuda_runtime.h>
#include <math.h>

#define VV 3
#define CC 32
#define DD 48
#define HH 128
#define WW 160
#define HW (HH*WW)        /* 20480 */
#define DHW (DD*HW)       /* 983040 */

// ---------------------------------------------------------------------------
// Scratch
// ---------------------------------------------------------------------------
__device__ float g_xform[2][12];
__device__ float g_feat_t[(size_t)VV*HW*CC];     // channels-last features
__device__ float g_var[(size_t)DHW*CC];          // variance volume [D,H,W,32]
__device__ float g_h0[(size_t)DHW*8];            // conv0 out [D,H,W,8]
__device__ float g_h1[(size_t)DHW*8];            // conv1 out [D,H,W,8]
__device__ float g_cost[(size_t)DHW];            // conv2 out [D,H,W]

__device__ __forceinline__ unsigned tf32cvt(float f) {
    unsigned u;
    asm("cvt.rna.tf32.f32 %0, %1;" : "=r"(u) : "f"(f));
    return u;
}

// D(16x8) += A(16x8) * B(8x8), tf32 operands, f32 accum
__device__ __forceinline__ void mma_tf32(float* d, const unsigned* a, const unsigned* b) {
    asm("mma.sync.aligned.m16n8k8.row.col.f32.tf32.tf32.f32 "
        "{%0,%1,%2,%3}, {%4,%5,%6,%7}, {%8,%9}, {%0,%1,%2,%3};"
        : "+f"(d[0]), "+f"(d[1]), "+f"(d[2]), "+f"(d[3])
        : "r"(a[0]), "r"(a[1]), "r"(a[2]), "r"(a[3]), "r"(b[0]), "r"(b[1]));
}

// ---------------------------------------------------------------------------
// Kernel 1: projective transforms  M_v = C_v * inv(C_0)
// ---------------------------------------------------------------------------
__global__ void k_xform(const float* __restrict__ proj) {
    if (threadIdx.x || blockIdx.x) return;
    double Cm[3][4][4];
    for (int v = 0; v < 3; ++v) {
        double K[3][3], E[4][4];
        for (int i = 0; i < 3; ++i)
            for (int j = 0; j < 3; ++j)
                K[i][j] = (double)proj[((v*2+1)*4+i)*4+j];
        for (int i = 0; i < 4; ++i)
            for (int j = 0; j < 4; ++j)
                E[i][j] = (double)proj[((v*2+0)*4+i)*4+j];
        for (int i = 0; i < 3; ++i)
            for (int j = 0; j < 4; ++j) {
                double s = 0.0;
                for (int k = 0; k < 3; ++k) s += K[i][k]*E[k][j];
                Cm[v][i][j] = s;
            }
        for (int j = 0; j < 4; ++j) Cm[v][3][j] = E[3][j];
    }
    double A[4][8];
    for (int i = 0; i < 4; ++i)
        for (int j = 0; j < 4; ++j) { A[i][j] = Cm[0][i][j]; A[i][4+j] = (i==j) ? 1.0 : 0.0; }
    for (int col = 0; col < 4; ++col) {
        int piv = col;
        for (int r = col+1; r < 4; ++r) if (fabs(A[r][col]) > fabs(A[piv][col])) piv = r;
        if (piv != col)
            for (int j = 0; j < 8; ++j) { double t = A[col][j]; A[col][j] = A[piv][j]; A[piv][j] = t; }
        double iv = 1.0 / A[col][col];
        for (int j = 0; j < 8; ++j) A[col][j] *= iv;
        for (int r = 0; r < 4; ++r) if (r != col) {
            double f = A[r][col];
            for (int j = 0; j < 8; ++j) A[r][j] -= f * A[col][j];
        }
    }
    for (int v = 1; v < 3; ++v) {
        double M[3][4];
        for (int i = 0; i < 3; ++i)
            for (int j = 0; j < 4; ++j) {
                double s = 0.0;
                for (int k = 0; k < 4; ++k) s += Cm[v][i][k] * A[k][4+j];
                M[i][j] = s;
            }
        float* o = g_xform[v-1];
        o[0]=(float)M[0][0]; o[1]=(float)M[0][1]; o[2]=(float)M[0][2];
        o[3]=(float)M[1][0]; o[4]=(float)M[1][1]; o[5]=(float)M[1][2];
        o[6]=(float)M[2][0]; o[7]=(float)M[2][1]; o[8]=(float)M[2][2];
        o[9]=(float)M[0][3]; o[10]=(float)M[1][3]; o[11]=(float)M[2][3];
    }
}

// ---------------------------------------------------------------------------
// Kernel 2: tiled transpose [V,C,H,W] -> [V,H,W,C]
// ---------------------------------------------------------------------------
__global__ void k_transpose(const float* __restrict__ f) {
    __shared__ float t[32][33];
    int v   = blockIdx.y;
    int hw0 = blockIdx.x * 32;
    for (int i = threadIdx.y; i < 32; i += 8)
        t[i][threadIdx.x] = f[((size_t)v*32 + i)*HW + hw0 + threadIdx.x];
    __syncthreads();
    for (int i = threadIdx.y; i < 32; i += 8)
        g_feat_t[((size_t)v*HW + hw0 + i)*32 + threadIdx.x] = t[threadIdx.x][i];
}

// ---------------------------------------------------------------------------
// Kernel 3: warp+variance, lane-per-channel-group layout
// ---------------------------------------------------------------------------
__global__ void __launch_bounds__(256) k_warpvar(const float* __restrict__ dvals) {
    long long t = (long long)blockIdx.x*256 + threadIdx.x;
    int g   = (int)(t & 7);
    int idx = (int)(t >> 3);
    if (idx >= DHW) return;
    int w = idx % WW;
    int h = (idx / WW) % HH;
    float depth = dvals[idx];

    int   offs[2][4];
    float cwts[2][4];
    #pragma unroll
    for (int v = 0; v < 2; ++v) {
        const float* xf = g_xform[v];
        float x = (float)w, y = (float)h;
        float rx = xf[0]*x + xf[1]*y + xf[2];
        float ry = xf[3]*x + xf[4]*y + xf[5];
        float rz = xf[6]*x + xf[7]*y + xf[8];
        float px = rx*depth + xf[9];
        float py = ry*depth + xf[10];
        float pz = rz*depth + xf[11];
        float gx = px / pz / ((float)(WW-1)*0.5f) - 1.0f;
        float gy = py / pz / ((float)(HH-1)*0.5f) - 1.0f;
        float sx = (gx + 1.0f) * 0.5f * (float)(WW-1);
        float sy = (gy + 1.0f) * 0.5f * (float)(HH-1);
        float x0 = floorf(sx), y0 = floorf(sy);
        float wx1 = sx - x0, wx0 = 1.0f - wx1;
        float wy1 = sy - y0, wy0 = 1.0f - wy1;
        float cx[2] = {x0, x0+1.0f}, cy[2] = {y0, y0+1.0f};
        float wx[2] = {wx0, wx1}, wy[2] = {wy0, wy1};
        #pragma unroll
        for (int cyi = 0; cyi < 2; ++cyi)
        #pragma unroll
        for (int cxi = 0; cxi < 2; ++cxi) {
            float xi = cx[cxi], yi = cy[cyi];
            bool valid = (xi >= 0.0f) && (xi <= (float)(WW-1)) &&
                         (yi >= 0.0f) && (yi <= (float)(HH-1));
            float xc = fminf(fmaxf(xi, 0.0f), (float)(WW-1));
            float yc = fminf(fmaxf(yi, 0.0f), (float)(HH-1));
            int ii = (int)yc * WW + (int)xc;
            offs[v][cyi*2+cxi] = ii * CC + g*4;
            cwts[v][cyi*2+cxi] = wx[cxi]*wy[cyi] * (valid ? 1.0f : 0.0f);
        }
    }

    float4 r = *(const float4*)(g_feat_t + (size_t)(h*WW + w)*CC + g*4);
    const float* s1 = g_feat_t + (size_t)HW*CC;
    const float* s2 = g_feat_t + (size_t)2*HW*CC;

    float sx_ = r.x, sy_ = r.y, sz_ = r.z, sw_ = r.w;
    float qx = r.x*r.x, qy = r.y*r.y, qz = r.z*r.z, qw = r.w*r.w;
    #pragma unroll
    for (int v = 0; v < 2; ++v) {
        const float* base = (v == 0) ? s1 : s2;
        float wxp = 0.f, wyp = 0.f, wzp = 0.f, wwp = 0.f;
        #pragma unroll
        for (int k = 0; k < 4; ++k) {
            float cw = cwts[v][k];
            const float4 f = *(const float4*)(base + offs[v][k]);
            wxp = fmaf(cw, f.x, wxp);
            wyp = fmaf(cw, f.y, wyp);
            wzp = fmaf(cw, f.z, wzp);
            wwp = fmaf(cw, f.w, wwp);
        }
        sx_ += wxp; sy_ += wyp; sz_ += wzp; sw_ += wwp;
        qx = fmaf(wxp, wxp, qx); qy = fmaf(wyp, wyp, qy);
        qz = fmaf(wzp, wzp, qz); qw = fmaf(wwp, wwp, qw);
    }
    float4 o;
    float mx = sx_ / 3.0f, my = sy_ / 3.0f, mz = sz_ / 3.0f, mw = sw_ / 3.0f;
    o.x = qx / 3.0f - mx*mx;
    o.y = qy / 3.0f - my*my;
    o.z = qz / 3.0f - mz*mz;
    o.w = qw / 3.0f - mw*mw;
    *(float4*)(g_var + (size_t)idx*CC + g*4) = o;
}

// ---------------------------------------------------------------------------
// Kernel 4: conv0 (32->8) via tf32 mma, tap-wise implicit GEMM.
// Block: 256 thr = 8 warps; warp = one h-row of 16 w's, DS=6 depth outputs.
// Slab: 8 slices, 10x18 pixels, 32ch, XOR-rotation swizzle (conflict-free frags).
// ---------------------------------------------------------------------------
__global__ void __launch_bounds__(256, 1)
k_conv0(const float* __restrict__ wgt, const float* __restrict__ bias) {
    constexpr int DS = 6, NSL = 8;
    constexpr int SLICE = 10*18*32;               // 5760 floats

    extern __shared__ float sm[];
    float* s_w  = sm;                             // [tap][cin 32][co 8] tf32
    float* slab = sm + 27*32*8;

    const int tid  = threadIdx.x;
    const int ty   = tid >> 5;                    // warp id = h row 0..7
    const int lane = tid & 31;
    const int gid  = lane >> 2;
    const int tig  = lane & 3;
    const int w0 = blockIdx.x * 16;
    const int h0 = blockIdx.y * 8;
    const int d0 = blockIdx.z * DS;

    // weights: s_w[tap*256 + cin*8 + co] = tf32(wgt[(co*32+cin)*27 + tap])
    for (int i = tid; i < 27*256; i += 256) {
        int co  = i & 7;
        int cin = (i >> 3) & 31;
        int tap = i >> 8;
        ((unsigned*)s_w)[i] = tf32cvt(wgt[(co*32 + cin)*27 + tap]);
    }
    // slab fill: group g of pixel pix at pix*32 + ((g ^ (pix&7))<<2), tf32
    {
        const int NTOT = NSL*10*18*8;
        for (int i = tid; i < NTOT; i += 256) {
            int g   = i & 7;
            int col = (i >> 3) % 18;
            int rem = i / (8*18);
            int row = rem % 10;
            int s   = rem / 10;
            int z  = d0 - 1 + s;
            int gh = h0 - 1 + row;
            int gw = w0 - 1 + col;
            float4 v = make_float4(0.f, 0.f, 0.f, 0.f);
            if (z >= 0 && z < DD && gh >= 0 && gh < HH && gw >= 0 && gw < WW)
                v = *(const float4*)(g_var + (((size_t)z*HH + gh)*WW + gw)*32 + g*4);
            int pix = row*18 + col;
            uint4 u = make_uint4(tf32cvt(v.x), tf32cvt(v.y), tf32cvt(v.z), tf32cvt(v.w));
            *(uint4*)(slab + s*SLICE + pix*32 + ((g ^ (pix & 7)) << 2)) = u;
        }
    }
    __syncthreads();

    float acc[DS][4];
    #pragma unroll
    for (int o = 0; o < DS; ++o)
        #pragma unroll
        for (int j = 0; j < 4; ++j) acc[o][j] = 0.f;

    #pragma unroll 1
    for (int kh = 0; kh < 3; ++kh) {
        #pragma unroll 1
        for (int kw = 0; kw < 3; ++kw) {
            const int p_lo = (ty+kh)*18 + kw + gid;
            const int p_hi = p_lo + 8;
            const unsigned* xlo = (const unsigned*)(slab) + p_lo*32 + tig;
            const unsigned* xhi = (const unsigned*)(slab) + p_hi*32 + tig;
            const int rlo = (p_lo & 7), rhi = (p_hi & 7);
            const unsigned* wb = (const unsigned*)(s_w) + (kh*3 + kw)*256;
            #pragma unroll
            for (int c = 0; c < 4; ++c) {
                unsigned a[NSL][4];
                const int glo0 = ((2*c)     ^ rlo) << 2;
                const int glo1 = ((2*c + 1) ^ rlo) << 2;
                const int ghi0 = ((2*c)     ^ rhi) << 2;
                const int ghi1 = ((2*c + 1) ^ rhi) << 2;
                #pragma unroll
                for (int s = 0; s < NSL; ++s) {
                    a[s][0] = xlo[s*SLICE + glo0];
                    a[s][1] = xhi[s*SLICE + ghi0];
                    a[s][2] = xlo[s*SLICE + glo1];
                    a[s][3] = xhi[s*SLICE + ghi1];
                }
                unsigned b[3][2];
                #pragma unroll
                for (int kd = 0; kd < 3; ++kd) {
                    const unsigned* wp = wb + kd*9*256 + (c*8 + tig)*8 + gid;
                    b[kd][0] = wp[0];
                    b[kd][1] = wp[32];        // (c*8+tig+4)*8+gid
                }
                #pragma unroll
                for (int kd = 0; kd < 3; ++kd)
                    #pragma unroll
                    for (int o = 0; o < DS; ++o)
                        mma_tf32(acc[o], a[o+kd], b[kd]);
            }
        }
    }

    const float b0 = bias[2*tig], b1 = bias[2*tig+1];
    #pragma unroll
    for (int o = 0; o < DS; ++o) {
        int d = d0 + o;
        float* row = g_h0 + (((size_t)d*HH + (h0+ty))*WW + w0)*8;
        float2 v0 = make_float2(fmaxf(acc[o][0] + b0, 0.f), fmaxf(acc[o][1] + b1, 0.f));
        float2 v1 = make_float2(fmaxf(acc[o][2] + b0, 0.f), fmaxf(acc[o][3] + b1, 0.f));
        *(float2*)(row + gid*8       + 2*tig) = v0;
        *(float2*)(row + (gid+8)*8   + 2*tig) = v1;
    }
}

// ---------------------------------------------------------------------------
// Kernels 5-6: conv1 (8->8) / conv2 (8->1 via zero-padded couts), tf32 mma.
// Slab PS=12 (bank-clean for fragment loads), 8 slices, 256 thr, 2 blocks/SM.
// ---------------------------------------------------------------------------
template<int STAGE>
__global__ void __launch_bounds__(256, 2)
k_conv(const float* __restrict__ wgt, const float* __restrict__ bias) {
    constexpr bool RELU = (STAGE != 2);
    constexpr int DS = 6, NSL = 8, PS = 12;
    constexpr int SLICE = 10*18*PS;               // 2160 floats

    const float* __restrict__ x   = (STAGE == 1) ? g_h0 : g_h1;
    float*       __restrict__ out = (STAGE == 1) ? g_h1 : g_cost;

    extern __shared__ float sm[];
    float* s_w  = sm;                             // [tap][cin 8][co 8]
    float* slab = sm + 27*64;

    const int tid  = threadIdx.x;
    const int ty   = tid >> 5;
    const int lane = tid & 31;
    const int gid  = lane >> 2;
    const int tig  = lane & 3;
    const int w0 = blockIdx.x * 16;
    const int h0 = blockIdx.y * 8;
    const int d0 = blockIdx.z * DS;

    for (int i = tid; i < 27*64; i += 256) {
        int co  = i & 7;
        int cin = (i >> 3) & 7;
        int tap = i >> 6;
        float wv;
        if (STAGE == 1) wv = wgt[(co*8 + cin)*27 + tap];
        else            wv = (co == 0) ? wgt[cin*27 + tap] : 0.f;
        ((unsigned*)s_w)[i] = tf32cvt(wv);
    }
    {
        const int NTOT = NSL*10*18*2;             // float4 units
        for (int i = tid; i < NTOT; i += 256) {
            int g   = i & 1;
            int col = (i >> 1) % 18;
            int rem = i / (2*18);
            int row = rem % 10;
            int s   = rem / 10;
            int z  = d0 - 1 + s;
            int gh = h0 - 1 + row;
            int gw = w0 - 1 + col;
            float4 v = make_float4(0.f, 0.f, 0.f, 0.f);
            if (z >= 0 && z < DD && gh >= 0 && gh < HH && gw >= 0 && gw < WW)
                v = *(const float4*)(x + (((size_t)z*HH + gh)*WW + gw)*8 + g*4);
            uint4 u = make_uint4(tf32cvt(v.x), tf32cvt(v.y), tf32cvt(v.z), tf32cvt(v.w));
            *(uint4*)(slab + (s*180 + row*18 + col)*PS + g*4) = u;
        }
    }
    __syncthreads();

    float acc[DS][4];
    #pragma unroll
    for (int o = 0; o < DS; ++o)
        #pragma unroll
        for (int j = 0; j < 4; ++j) acc[o][j] = 0.f;

    #pragma unroll 1
    for (int kh = 0; kh < 3; ++kh) {
        #pragma unroll 1
        for (int kw = 0; kw < 3; ++kw) {
            const int p_lo = (ty+kh)*18 + kw + gid;
            const unsigned* xlo = (const unsigned*)(slab) + p_lo*PS + tig;
            const unsigned* xhi = xlo + 8*PS;
            const unsigned* wb = (const unsigned*)(s_w) + (kh*3 + kw)*64;
            unsigned a[NSL][4];
            #pragma unroll
            for (int s = 0; s < NSL; ++s) {
                a[s][0] = xlo[s*SLICE];
                a[s][1] = xhi[s*SLICE];
                a[s][2] = xlo[s*SLICE + 4];
                a[s][3] = xhi[s*SLICE + 4];
            }
            unsigned b[3][2];
            #pragma unroll
            for (int kd = 0; kd < 3; ++kd) {
                const unsigned* wp = wb + kd*9*64 + tig*8 + gid;
                b[kd][0] = wp[0];
                b[kd][1] = wp[32];
            }
            #pragma unroll
            for (int kd = 0; kd < 3; ++kd)
                #pragma unroll
                for (int o = 0; o < DS; ++o)
                    mma_tf32(acc[o], a[o+kd], b[kd]);
        }
    }

    if (STAGE == 1) {
        const float b0 = bias[2*tig], b1 = bias[2*tig+1];
        #pragma unroll
        for (int o = 0; o < DS; ++o) {
            int d = d0 + o;
            float* row = out + (((size_t)d*HH + (h0+ty))*WW + w0)*8;
            float2 v0 = make_float2(fmaxf(acc[o][0] + b0, 0.f), fmaxf(acc[o][1] + b1, 0.f));
            float2 v1 = make_float2(fmaxf(acc[o][2] + b0, 0.f), fmaxf(acc[o][3] + b1, 0.f));
            *(float2*)(row + gid*8     + 2*tig) = v0;
            *(float2*)(row + (gid+8)*8 + 2*tig) = v1;
        }
    } else {
        const float b0 = bias[0];
        if (tig == 0) {
            #pragma unroll
            for (int o = 0; o < DS; ++o) {
                int d = d0 + o;
                float* row = out + ((size_t)d*HH + (h0+ty))*WW + w0;
                row[gid]     = acc[o][0] + b0;
                row[gid+8]   = acc[o][2] + b0;
            }
        }
    }
}

// ---------------------------------------------------------------------------
// Kernel 7: softmax over D + expected depth + 4-tap confidence
// ---------------------------------------------------------------------------
__global__ void k_softmax(const float* __restrict__ dvals, float* __restrict__ out) {
    int p = blockIdx.x*blockDim.x + threadIdx.x;
    if (p >= HW) return;
    float c[DD];
    float m = -1e30f;
    #pragma unroll
    for (int d = 0; d < DD; ++d) { c[d] = g_cost[(size_t)d*HW + p]; m = fmaxf(m, c[d]); }
    float S = 0.f;
    #pragma unroll
    for (int d = 0; d < DD; ++d) { c[d] = expf(c[d] - m); S += c[d]; }
    float inv = 1.0f / S;
    float depth = 0.f, fid = 0.f;
    #pragma unroll
    for (int d = 0; d < DD; ++d) {
        float pr = c[d] * inv;
        depth = fmaf(pr, dvals[(size_t)d*HW + p], depth);
        fid   = fmaf(pr, (float)d, fid);
    }
    int di = (int)fid;
    di = max(0, min(DD-1, di));
    float conf = 0.f;
    #pragma unroll
    for (int d = 0; d < DD; ++d)
        if (d >= di-1 && d <= di+2) conf += c[d] * inv;
    out[p]      = depth;
    out[HW + p] = conf;
}

// ---------------------------------------------------------------------------
// Launch
// ---------------------------------------------------------------------------
extern "C" void kernel_launch(void* const* d_in, const int* in_sizes, int n_in,
                              void* d_out, int out_size) {
    const float* features = (const float*)d_in[0];
    const float* proj     = (const float*)d_in[1];
    const float* dvals    = (const float*)d_in[2];
    const float* w0 = (const float*)d_in[3];
    const float* b0 = (const float*)d_in[4];
    const float* w1 = (const float*)d_in[5];
    const float* b1 = (const float*)d_in[6];
    const float* w2 = (const float*)d_in[7];
    const float* b2 = (const float*)d_in[8];
    float* out = (float*)d_out;

    const int smem0 = (27*256 + 8*5760) * 4;    // 27648 + 184320 = 211968 B
    const int smem12 = (27*64 + 8*2160) * 4;    //  6912 +  69120 =  76032 B
    cudaFuncSetAttribute(k_conv0,   cudaFuncAttributeMaxDynamicSharedMemorySize, smem0);
    cudaFuncSetAttribute(k_conv<1>, cudaFuncAttributeMaxDynamicSharedMemorySize, smem12);
    cudaFuncSetAttribute(k_conv<2>, cudaFuncAttributeMaxDynamicSharedMemorySize, smem12);

    k_xform<<<1, 1>>>(proj);
    dim3 tgrid(HW/32, VV);
    k_transpose<<<tgrid, dim3(32, 8)>>>(features);
    k_warpvar<<<(DHW*8)/256, 256>>>(dvals);

    dim3 cgrid(WW/16, HH/8, DD/6);   // (10, 16, 8)
    k_conv0<<<cgrid, 256, smem0>>>(w0, b0);
    k_conv<1><<<cgrid, 256, smem12>>>(w1, b1);
    k_conv<2><<<cgrid, 256, smem12>>>(w2, b2);

    k_softmax<<<(HW + 255)/256, 256>>>(dvals, out);
}